// round 14
// baseline (speedup 1.0000x reference)
#include <cuda_runtime.h>
#include <math.h>

#define NN 50000
#define NE 800000
#define NB 64

#define PREP_B 3125      // (NE+255)/256
#define CNT_B  196       // (NN+255)/256
#define ENC_B  782       // (NN+63)/64
#define PH1_B  (PREP_B + CNT_B + 1 + ENC_B)   // 4104
#define FILL_B 3125
#define G2X    391       // (NN+127)/128
#define PH3_B  (FILL_B + G2X * 4)             // 4689

// ---------------- scratch ---------------------------------------------------------
__device__ int   g_is64;
__device__ int   g_deg[NN];
__device__ int   g_cursor[NN];
__device__ int   g_rowptr[NN + 1];
__device__ int   g_src[NE];
__device__ int   g_dst[NE];
__device__ int   g_esrc[NE];
__device__ __align__(16) float g_eatt[NE * 8];
__device__ __align__(16) float g_loop8[NN * 8];
__device__ float g_ebs[NN];
__device__ __align__(16) float g_h0[NN * 64];
__device__ __align__(16) float g_xl1[NN * 256];
__device__ __align__(16) float g_xr1[NN * 256];
__device__ __align__(16) float g_h1[NN * 256];
__device__ __align__(16) float g_xl2[NN * 64];
__device__ __align__(16) float g_xr2[NN * 64];
__device__ __align__(16) float g_EW1[8 * 256];
__device__ float g_eb1[256];
__device__ __align__(16) float g_EW2[8 * 64];
__device__ float g_eb2[64];
__device__ float g_pool[NB * 64];
__device__ float g_cnt[NB];

__device__ __forceinline__ int load_idx(const void* p, long long i, int is64) {
    if (is64) return (int)((const long long*)p)[i];
    return ((const int*)p)[i];
}

// ---------------- L0: detect dtype + zero accumulators ------------------------------
__global__ void k_init(const int* __restrict__ ei_w) {
    if (blockIdx.x == 0 && threadIdx.x < 32) {
        int v = ei_w[threadIdx.x * 2 + 1];
        unsigned any = __ballot_sync(0xffffffffu, v != 0);
        if (threadIdx.x == 0) g_is64 = (any == 0u) ? 1 : 0;
    }
    int i = blockIdx.x * blockDim.x + threadIdx.x;
    int stride = gridDim.x * blockDim.x;
    for (int t = i; t < NN; t += stride) { g_deg[t] = 0; g_cursor[t] = 0; }
    for (int t = i; t < NB * 64; t += stride) g_pool[t] = 0.f;
    for (int t = i; t < NB; t += stride) g_cnt[t] = 0.f;
}

// ---------------- device pieces for mega-launches ------------------------------------
__device__ void dev_prep(const void* __restrict__ ei, int b) {
    int e = b * 256 + threadIdx.x;
    if (e >= NE) return;
    int is64 = g_is64;
    int s = load_idx(ei, e, is64);
    int d = load_idx(ei, (long long)NE + e, is64);
    s = min(max(s, 0), NN - 1);
    d = min(max(d, 0), NN - 1);
    g_src[e] = s;
    g_dst[e] = d;
    atomicAdd(&g_deg[d], 1);
}

__device__ void dev_cnt(const void* __restrict__ batch, int b) {
    __shared__ int h[NB];
    int tid = threadIdx.x;
    if (tid < NB) h[tid] = 0;
    __syncthreads();
    int n = b * 256 + tid;
    if (n < NN) {
        int bb = load_idx(batch, n, g_is64);
        bb = min(max(bb, 0), NB - 1);
        atomicAdd(&h[bb], 1);
    }
    __syncthreads();
    if (tid < NB && h[tid]) atomicAdd(&g_cnt[tid], (float)h[tid]);
}

__device__ void dev_smallw(const float* __restrict__ W_edge, const float* __restrict__ b_edge,
                           const float* __restrict__ We1, const float* __restrict__ We2) {
    __shared__ float sWe[8 * 64];
    __shared__ float sbe[64];
    int t = threadIdx.x;
    if (t < 64) sbe[t] = b_edge[t];
    for (int i = t; i < 512; i += 256) sWe[i] = W_edge[i];
    __syncthreads();
    {
        float acc[8] = {0, 0, 0, 0, 0, 0, 0, 0};
        float accb = 0.f;
        for (int k = 0; k < 64; k++) {
            float w = We1[k * 256 + t];
            accb += sbe[k] * w;
#pragma unroll
            for (int j = 0; j < 8; j++) acc[j] += sWe[j * 64 + k] * w;
        }
#pragma unroll
        for (int j = 0; j < 8; j++) g_EW1[j * 256 + t] = acc[j];
        g_eb1[t] = accb;
    }
    if (t < 64) {
        float acc[8] = {0, 0, 0, 0, 0, 0, 0, 0};
        float accb = 0.f;
        for (int k = 0; k < 64; k++) {
            float w = We2[k * 64 + t];
            accb += sbe[k] * w;
#pragma unroll
            for (int j = 0; j < 8; j++) acc[j] += sWe[j * 64 + k] * w;
        }
#pragma unroll
        for (int j = 0; j < 8; j++) g_EW2[j * 64 + t] = acc[j];
        g_eb2[t] = accb;
    }
}

// encoder GEMM tile: C[row0:+64, 0:64] = A[.,0:16] @ W + bias
__device__ void dev_gemm_enc(const float* __restrict__ A, const float* __restrict__ W,
                             const float* __restrict__ bias, float* __restrict__ C, int row0) {
    const int K = 16, Cc = 64;
    __shared__ float sA[64][17];
    __shared__ float sW[16][64];
    int tid = threadIdx.x;
    int tx = tid & 15, ty = tid >> 4;
#pragma unroll
    for (int i = tid; i < 1024; i += 256) {
        int r = i >> 4, kk = i & 15;
        int m = row0 + r;
        sA[r][kk] = (m < NN) ? A[(size_t)m * K + kk] : 0.f;
    }
#pragma unroll
    for (int i = tid; i < 1024; i += 256) {
        int kk = i >> 6, c = i & 63;
        sW[kk][c] = W[(size_t)kk * Cc + c];
    }
    __syncthreads();
    float acc[4][4] = {};
#pragma unroll
    for (int kk = 0; kk < 16; kk++) {
        float4 wv = *reinterpret_cast<const float4*>(&sW[kk][tx * 4]);
        float a0 = sA[ty * 4 + 0][kk];
        float a1 = sA[ty * 4 + 1][kk];
        float a2 = sA[ty * 4 + 2][kk];
        float a3 = sA[ty * 4 + 3][kk];
        acc[0][0] += a0 * wv.x; acc[0][1] += a0 * wv.y; acc[0][2] += a0 * wv.z; acc[0][3] += a0 * wv.w;
        acc[1][0] += a1 * wv.x; acc[1][1] += a1 * wv.y; acc[1][2] += a1 * wv.z; acc[1][3] += a1 * wv.w;
        acc[2][0] += a2 * wv.x; acc[2][1] += a2 * wv.y; acc[2][2] += a2 * wv.z; acc[2][3] += a2 * wv.w;
        acc[3][0] += a3 * wv.x; acc[3][1] += a3 * wv.y; acc[3][2] += a3 * wv.z; acc[3][3] += a3 * wv.w;
    }
    float b0 = bias[tx * 4 + 0], b1 = bias[tx * 4 + 1];
    float b2 = bias[tx * 4 + 2], b3 = bias[tx * 4 + 3];
#pragma unroll
    for (int i = 0; i < 4; i++) {
        int m = row0 + ty * 4 + i;
        if (m < NN)
            *reinterpret_cast<float4*>(&C[(size_t)m * Cc + tx * 4]) =
                make_float4(acc[i][0] + b0, acc[i][1] + b1, acc[i][2] + b2, acc[i][3] + b3);
    }
}

// ---------------- L1 mega: prep + cnt + smallw + encoder GEMM ------------------------
__global__ void __launch_bounds__(256) k_phase1(const void* __restrict__ ei,
                                                const void* __restrict__ batch,
                                                const float* __restrict__ x,
                                                const float* __restrict__ W_node,
                                                const float* __restrict__ b_node,
                                                const float* __restrict__ W_edge,
                                                const float* __restrict__ b_edge,
                                                const float* __restrict__ We1,
                                                const float* __restrict__ We2) {
    int b = blockIdx.x;
    if (b < PREP_B)                       dev_prep(ei, b);
    else if (b < PREP_B + CNT_B)          dev_cnt(batch, b - PREP_B);
    else if (b == PREP_B + CNT_B)         dev_smallw(W_edge, b_edge, We1, We2);
    else                                  dev_gemm_enc(x, W_node, b_node, g_h0,
                                                       (b - PREP_B - CNT_B - 1) * 64);
}

// ---------------- L2: exclusive scan deg -> rowptr ------------------------------------
__global__ void k_scan() {
    __shared__ int warpsums[32];
    __shared__ int s_carry;
    int tid = threadIdx.x;
    int lane = tid & 31, wid = tid >> 5;
    if (tid == 0) { g_rowptr[0] = 0; s_carry = 0; }
    __syncthreads();
    for (int base = 0; base < NN; base += 1024) {
        int i = base + tid;
        int v = (i < NN) ? g_deg[i] : 0;
        int x = v;
#pragma unroll
        for (int off = 1; off < 32; off <<= 1) {
            int y = __shfl_up_sync(0xffffffffu, x, off);
            if (lane >= off) x += y;
        }
        if (lane == 31) warpsums[wid] = x;
        __syncthreads();
        if (wid == 0) {
            int w = warpsums[lane];
#pragma unroll
            for (int off = 1; off < 32; off <<= 1) {
                int y = __shfl_up_sync(0xffffffffu, w, off);
                if (lane >= off) w += y;
            }
            warpsums[lane] = w;
        }
        __syncthreads();
        int excl = s_carry + ((wid > 0) ? warpsums[wid - 1] : 0);
        int incl = excl + x;
        if (i < NN) g_rowptr[i + 1] = incl;
        __syncthreads();
        if (tid == 0) s_carry += warpsums[31];
        __syncthreads();
    }
}

// ---------------- dual GEMM tile (128x64, 2 outputs) -----------------------------------
__device__ void dev_gemm2(const float* __restrict__ A,
                          const float* __restrict__ W1, const float* __restrict__ b1,
                          const float* __restrict__ W2, const float* __restrict__ b2,
                          float* __restrict__ C1, float* __restrict__ C2,
                          int K, int Cc, int row0, int col0) {
    __shared__ __align__(16) float sA[16][132];
    __shared__ __align__(16) float sW[2][16][64];
    int tid = threadIdx.x;
    int tx = tid & 15, ty = tid >> 4;

    float acc1[8][4] = {}, acc2[8][4] = {};
    for (int k0 = 0; k0 < K; k0 += 16) {
#pragma unroll
        for (int p = 0; p < 2; p++) {
            int r = p * 64 + (tid >> 2);
            int kv = (tid & 3) * 4;
            int m = row0 + r;
            float4 v = make_float4(0.f, 0.f, 0.f, 0.f);
            if (m < NN) v = *reinterpret_cast<const float4*>(&A[(size_t)m * K + k0 + kv]);
            sA[kv + 0][r] = v.x;
            sA[kv + 1][r] = v.y;
            sA[kv + 2][r] = v.z;
            sA[kv + 3][r] = v.w;
        }
        {
            int kk = tid >> 4, c = (tid & 15) * 4;
            size_t off = (size_t)(k0 + kk) * Cc + col0 + c;
            *reinterpret_cast<float4*>(&sW[0][kk][c]) = *reinterpret_cast<const float4*>(&W1[off]);
            *reinterpret_cast<float4*>(&sW[1][kk][c]) = *reinterpret_cast<const float4*>(&W2[off]);
        }
        __syncthreads();
#pragma unroll
        for (int kk = 0; kk < 16; kk++) {
            float4 a0 = *reinterpret_cast<const float4*>(&sA[kk][ty * 8]);
            float4 a1 = *reinterpret_cast<const float4*>(&sA[kk][ty * 8 + 4]);
            float4 w1 = *reinterpret_cast<const float4*>(&sW[0][kk][tx * 4]);
            float4 w2 = *reinterpret_cast<const float4*>(&sW[1][kk][tx * 4]);
            float ar[8] = {a0.x, a0.y, a0.z, a0.w, a1.x, a1.y, a1.z, a1.w};
#pragma unroll
            for (int r = 0; r < 8; r++) {
                acc1[r][0] = fmaf(ar[r], w1.x, acc1[r][0]);
                acc1[r][1] = fmaf(ar[r], w1.y, acc1[r][1]);
                acc1[r][2] = fmaf(ar[r], w1.z, acc1[r][2]);
                acc1[r][3] = fmaf(ar[r], w1.w, acc1[r][3]);
                acc2[r][0] = fmaf(ar[r], w2.x, acc2[r][0]);
                acc2[r][1] = fmaf(ar[r], w2.y, acc2[r][1]);
                acc2[r][2] = fmaf(ar[r], w2.z, acc2[r][2]);
                acc2[r][3] = fmaf(ar[r], w2.w, acc2[r][3]);
            }
        }
        __syncthreads();
    }
    float b1v0 = b1[col0 + tx * 4 + 0], b1v1 = b1[col0 + tx * 4 + 1];
    float b1v2 = b1[col0 + tx * 4 + 2], b1v3 = b1[col0 + tx * 4 + 3];
    float b2v0 = b2[col0 + tx * 4 + 0], b2v1 = b2[col0 + tx * 4 + 1];
    float b2v2 = b2[col0 + tx * 4 + 2], b2v3 = b2[col0 + tx * 4 + 3];
#pragma unroll
    for (int r = 0; r < 8; r++) {
        int m = row0 + ty * 8 + r;
        if (m < NN) {
            *reinterpret_cast<float4*>(&C1[(size_t)m * Cc + col0 + tx * 4]) =
                make_float4(acc1[r][0] + b1v0, acc1[r][1] + b1v1, acc1[r][2] + b1v2, acc1[r][3] + b1v3);
            *reinterpret_cast<float4*>(&C2[(size_t)m * Cc + col0 + tx * 4]) =
                make_float4(acc2[r][0] + b2v0, acc2[r][1] + b2v1, acc2[r][2] + b2v2, acc2[r][3] + b2v3);
        }
    }
}

__device__ void dev_fill(const float* __restrict__ eattr, int b) {
    int e = b * 256 + threadIdx.x;
    if (e >= NE) return;
    int d = g_dst[e];
    int p = g_rowptr[d] + atomicAdd(&g_cursor[d], 1);
    g_esrc[p] = g_src[e];
    float a[8];
#pragma unroll
    for (int j = 0; j < 8; j++) a[j] = eattr[e * 8 + j];
    reinterpret_cast<float4*>(g_eatt)[p * 2] = make_float4(a[0], a[1], a[2], a[3]);
    reinterpret_cast<float4*>(g_eatt)[p * 2 + 1] = make_float4(a[4], a[5], a[6], a[7]);
}

// ---------------- L3 mega: CSR fill + conv1-transform dual GEMM ------------------------
__global__ void __launch_bounds__(256) k_phase3(const float* __restrict__ eattr,
                                                const float* __restrict__ Wl1,
                                                const float* __restrict__ bl1,
                                                const float* __restrict__ Wr1,
                                                const float* __restrict__ br1) {
    int b = blockIdx.x;
    if (b < FILL_B) { dev_fill(eattr, b); return; }
    int idx = b - FILL_B;
    int bx = idx % G2X, by = idx / G2X;
    dev_gemm2(g_h0, Wl1, bl1, Wr1, br1, g_xl1, g_xr1, 64, 256, bx * 128, by * 64);
}

// ---------------- self-loop mean attrs --------------------------------------------------
__global__ void __launch_bounds__(256) k_loopattr() {
    int lane = threadIdx.x & 31;
    int d = blockIdx.x * 8 + (threadIdx.x >> 5);
    if (d >= NN) return;
    int beg = g_rowptr[d], end = g_rowptr[d + 1];
    float s = 0.f;
    for (int i = beg + (lane >> 3); i < end; i += 4)
        s += g_eatt[(size_t)i * 8 + (lane & 7)];
    s += __shfl_xor_sync(0xffffffffu, s, 8);
    s += __shfl_xor_sync(0xffffffffu, s, 16);
    int dg = end - beg;
    if (lane < 8) g_loop8[d * 8 + lane] = s / (float)max(dg, 1);
    if (lane == 0) g_ebs[d] = (dg > 0) ? 1.0f : 0.0f;
}

// ---------------- L5: conv2-transform dual GEMM ----------------------------------------
__global__ void __launch_bounds__(256) k_gemm2b(const float* __restrict__ Wl2,
                                                const float* __restrict__ bl2,
                                                const float* __restrict__ Wr2,
                                                const float* __restrict__ br2) {
    dev_gemm2(g_h1, Wl2, bl2, Wr2, br2, g_xl2, g_xr2, 256, 64, blockIdx.x * 128, 0);
}

// ---------------- conv1: warp-per-dst, EDGE-QUAD unroll (quarter LDS crossbar) ----------
__device__ __forceinline__ void conv1_logits_single(const float (&xls)[8], const float (&attr)[8],
                                                    float ebsc, const float (&xr)[8], int lane,
                                                    const float* __restrict__ sEW,
                                                    const float* __restrict__ seb,
                                                    const float* __restrict__ satt,
                                                    float (&out)[4]) {
    float p[4] = {0.f, 0.f, 0.f, 0.f};
#pragma unroll
    for (int t = 0; t < 8; t++) {
        int c = lane + 32 * t;
        float ep = ebsc * seb[c];
#pragma unroll
        for (int j = 0; j < 8; j++) ep += attr[j] * sEW[j * 256 + c];
        float v = xls[t] + xr[t] + ep;
        float m = v > 0.f ? v : 0.2f * v;
        p[t >> 1] += m * satt[(t >> 1) * 64 + (c & 63)];
    }
#pragma unroll
    for (int h = 0; h < 4; h++) {
#pragma unroll
        for (int off = 16; off > 0; off >>= 1)
            p[h] += __shfl_xor_sync(0xffffffffu, p[h], off);
        out[h] = p[h];
    }
}

__global__ void __launch_bounds__(256) k_conv1(const float* __restrict__ att1,
                                               const float* __restrict__ bias1) {
    __shared__ float sEW[2048];
    __shared__ float seb[256];
    __shared__ float satt[256];
    __shared__ float sbias[256];
    int tid = threadIdx.x;
    for (int i = tid; i < 2048; i += 256) sEW[i] = g_EW1[i];
    seb[tid] = g_eb1[tid];
    satt[tid] = att1[tid];
    sbias[tid] = bias1[tid];
    __syncthreads();

    int lane = tid & 31;
    int d = blockIdx.x * 8 + (tid >> 5);
    if (d >= NN) return;

    int beg = g_rowptr[d], end = g_rowptr[d + 1];

    float xr[8];
#pragma unroll
    for (int t = 0; t < 8; t++) xr[t] = g_xr1[(size_t)d * 256 + lane + 32 * t];

    float mx[4], dn[4], acc[8];
    // self loop initializes the online state
    {
        float xls[8];
        float4 a0 = *reinterpret_cast<const float4*>(&g_loop8[d * 8]);
        float4 a1 = *reinterpret_cast<const float4*>(&g_loop8[d * 8 + 4]);
        float attr[8] = {a0.x, a0.y, a0.z, a0.w, a1.x, a1.y, a1.z, a1.w};
#pragma unroll
        for (int t = 0; t < 8; t++) xls[t] = __ldg(&g_xl1[(size_t)d * 256 + lane + 32 * t]);
        float l[4];
        conv1_logits_single(xls, attr, g_ebs[d], xr, lane, sEW, seb, satt, l);
#pragma unroll
        for (int h = 0; h < 4; h++) { mx[h] = l[h]; dn[h] = 1.0f; }
#pragma unroll
        for (int t = 0; t < 8; t++) acc[t] = xls[t];
    }
    int i = beg;
    // edge QUADS: one sEW read serves four edges -> quarter crossbar traffic
    for (; i + 3 < end; i += 4) {
        int s1 = g_esrc[i], s2 = g_esrc[i + 1], s3 = g_esrc[i + 2], s4 = g_esrc[i + 3];
        float4 a10 = *reinterpret_cast<const float4*>(&g_eatt[(size_t)i * 8]);
        float4 a11 = *reinterpret_cast<const float4*>(&g_eatt[(size_t)i * 8 + 4]);
        float4 a20 = *reinterpret_cast<const float4*>(&g_eatt[(size_t)(i + 1) * 8]);
        float4 a21 = *reinterpret_cast<const float4*>(&g_eatt[(size_t)(i + 1) * 8 + 4]);
        float4 a30 = *reinterpret_cast<const float4*>(&g_eatt[(size_t)(i + 2) * 8]);
        float4 a31 = *reinterpret_cast<const float4*>(&g_eatt[(size_t)(i + 2) * 8 + 4]);
        float4 a40 = *reinterpret_cast<const float4*>(&g_eatt[(size_t)(i + 3) * 8]);
        float4 a41 = *reinterpret_cast<const float4*>(&g_eatt[(size_t)(i + 3) * 8 + 4]);
        float at1[8] = {a10.x, a10.y, a10.z, a10.w, a11.x, a11.y, a11.z, a11.w};
        float at2[8] = {a20.x, a20.y, a20.z, a20.w, a21.x, a21.y, a21.z, a21.w};
        float at3[8] = {a30.x, a30.y, a30.z, a30.w, a31.x, a31.y, a31.z, a31.w};
        float at4[8] = {a40.x, a40.y, a40.z, a40.w, a41.x, a41.y, a41.z, a41.w};
        float x1[8], x2[8], x3[8], x4[8];
#pragma unroll
        for (int t = 0; t < 8; t++) {
            x1[t] = __ldg(&g_xl1[(size_t)s1 * 256 + lane + 32 * t]);
            x2[t] = __ldg(&g_xl1[(size_t)s2 * 256 + lane + 32 * t]);
            x3[t] = __ldg(&g_xl1[(size_t)s3 * 256 + lane + 32 * t]);
            x4[t] = __ldg(&g_xl1[(size_t)s4 * 256 + lane + 32 * t]);
        }
        float p1[4] = {0.f, 0.f, 0.f, 0.f};
        float p2[4] = {0.f, 0.f, 0.f, 0.f};
        float p3[4] = {0.f, 0.f, 0.f, 0.f};
        float p4[4] = {0.f, 0.f, 0.f, 0.f};
#pragma unroll
        for (int t = 0; t < 8; t++) {
            int c = lane + 32 * t;
            float eb = seb[c];
            float e1 = eb, e2 = eb, e3 = eb, e4 = eb;
#pragma unroll
            for (int j = 0; j < 8; j++) {
                float w = sEW[j * 256 + c];
                e1 = fmaf(at1[j], w, e1);
                e2 = fmaf(at2[j], w, e2);
                e3 = fmaf(at3[j], w, e3);
                e4 = fmaf(at4[j], w, e4);
            }
            float xrt = xr[t];
            float v1 = e1 + xrt + x1[t];
            float v2 = e2 + xrt + x2[t];
            float v3 = e3 + xrt + x3[t];
            float v4 = e4 + xrt + x4[t];
            v1 = fmaxf(v1, 0.2f * v1);
            v2 = fmaxf(v2, 0.2f * v2);
            v3 = fmaxf(v3, 0.2f * v3);
            v4 = fmaxf(v4, 0.2f * v4);
            float aw = satt[(t >> 1) * 64 + (c & 63)];
            p1[t >> 1] = fmaf(v1, aw, p1[t >> 1]);
            p2[t >> 1] = fmaf(v2, aw, p2[t >> 1]);
            p3[t >> 1] = fmaf(v3, aw, p3[t >> 1]);
            p4[t >> 1] = fmaf(v4, aw, p4[t >> 1]);
        }
#pragma unroll
        for (int h = 0; h < 4; h++) {
#pragma unroll
            for (int off = 16; off > 0; off >>= 1) {
                p1[h] += __shfl_xor_sync(0xffffffffu, p1[h], off);
                p2[h] += __shfl_xor_sync(0xffffffffu, p2[h], off);
                p3[h] += __shfl_xor_sync(0xffffffffu, p3[h], off);
                p4[h] += __shfl_xor_sync(0xffffffffu, p4[h], off);
            }
        }
        float a1h[4], a2h[4], a3h[4], a4h[4], mul[4];
#pragma unroll
        for (int h = 0; h < 4; h++) {
            float mnew = fmaxf(fmaxf(mx[h], fmaxf(p1[h], p2[h])), fmaxf(p3[h], p4[h]));
            mul[h] = __expf(mx[h] - mnew);
            a1h[h] = __expf(p1[h] - mnew);
            a2h[h] = __expf(p2[h] - mnew);
            a3h[h] = __expf(p3[h] - mnew);
            a4h[h] = __expf(p4[h] - mnew);
            dn[h] = fmaf(dn[h], mul[h], (a1h[h] + a2h[h]) + (a3h[h] + a4h[h]));
            mx[h] = mnew;
        }
#pragma unroll
        for (int t = 0; t < 8; t++) {
            int hh = t >> 1;
            float add = fmaf(a1h[hh], x1[t], a2h[hh] * x2[t]);
            add = fmaf(a3h[hh], x3[t], add);
            add = fmaf(a4h[hh], x4[t], add);
            acc[t] = fmaf(acc[t], mul[hh], add);
        }
    }
    // pair tail
    for (; i + 1 < end; i += 2) {
        int s1 = g_esrc[i], s2 = g_esrc[i + 1];
        float4 a10 = *reinterpret_cast<const float4*>(&g_eatt[(size_t)i * 8]);
        float4 a11 = *reinterpret_cast<const float4*>(&g_eatt[(size_t)i * 8 + 4]);
        float4 a20 = *reinterpret_cast<const float4*>(&g_eatt[(size_t)(i + 1) * 8]);
        float4 a21 = *reinterpret_cast<const float4*>(&g_eatt[(size_t)(i + 1) * 8 + 4]);
        float at1[8] = {a10.x, a10.y, a10.z, a10.w, a11.x, a11.y, a11.z, a11.w};
        float at2[8] = {a20.x, a20.y, a20.z, a20.w, a21.x, a21.y, a21.z, a21.w};
        float x1[8], x2[8];
#pragma unroll
        for (int t = 0; t < 8; t++) {
            x1[t] = __ldg(&g_xl1[(size_t)s1 * 256 + lane + 32 * t]);
            x2[t] = __ldg(&g_xl1[(size_t)s2 * 256 + lane + 32 * t]);
        }
        float p1[4] = {0.f, 0.f, 0.f, 0.f};
        float p2[4] = {0.f, 0.f, 0.f, 0.f};
#pragma unroll
        for (int t = 0; t < 8; t++) {
            int c = lane + 32 * t;
            float e1 = seb[c], e2 = e1;
#pragma unroll
            for (int j = 0; j < 8; j++) {
                float w = sEW[j * 256 + c];
                e1 = fmaf(at1[j], w, e1);
                e2 = fmaf(at2[j], w, e2);
            }
            float v1 = e1 + xr[t] + x1[t];
            float v2 = e2 + xr[t] + x2[t];
            v1 = fmaxf(v1, 0.2f * v1);
            v2 = fmaxf(v2, 0.2f * v2);
            float aw = satt[(t >> 1) * 64 + (c & 63)];
            p1[t >> 1] = fmaf(v1, aw, p1[t >> 1]);
            p2[t >> 1] = fmaf(v2, aw, p2[t >> 1]);
        }
#pragma unroll
        for (int h = 0; h < 4; h++) {
#pragma unroll
            for (int off = 16; off > 0; off >>= 1) {
                p1[h] += __shfl_xor_sync(0xffffffffu, p1[h], off);
                p2[h] += __shfl_xor_sync(0xffffffffu, p2[h], off);
            }
        }
        float a1h[4], a2h[4], mul[4];
#pragma unroll
        for (int h = 0; h < 4; h++) {
            float mnew = fmaxf(mx[h], fmaxf(p1[h], p2[h]));
            mul[h] = __expf(mx[h] - mnew);
            a1h[h] = __expf(p1[h] - mnew);
            a2h[h] = __expf(p2[h] - mnew);
            dn[h] = fmaf(dn[h], mul[h], a1h[h] + a2h[h]);
            mx[h] = mnew;
        }
#pragma unroll
        for (int t = 0; t < 8; t++)
            acc[t] = fmaf(acc[t], mul[t >> 1], fmaf(a1h[t >> 1], x1[t], a2h[t >> 1] * x2[t]));
    }
    // single tail
    if (i < end) {
        int s = g_esrc[i];
        float4 a0 = *reinterpret_cast<const float4*>(&g_eatt[(size_t)i * 8]);
        float4 a1 = *reinterpret_cast<const float4*>(&g_eatt[(size_t)i * 8 + 4]);
        float attr[8] = {a0.x, a0.y, a0.z, a0.w, a1.x, a1.y, a1.z, a1.w};
        float xls[8];
#pragma unroll
        for (int t = 0; t < 8; t++) xls[t] = __ldg(&g_xl1[(size_t)s * 256 + lane + 32 * t]);
        float l[4];
        conv1_logits_single(xls, attr, 1.0f, xr, lane, sEW, seb, satt, l);
        float a[4], mul[4];
#pragma unroll
        for (int h = 0; h < 4; h++) {
            float mnew = fmaxf(mx[h], l[h]);
            mul[h] = __expf(mx[h] - mnew);
            a[h]   = __expf(l[h] - mnew);
            dn[h]  = fmaf(dn[h], mul[h], a[h]);
            mx[h]  = mnew;
        }
#pragma unroll
        for (int t = 0; t < 8; t++) acc[t] = fmaf(acc[t], mul[t >> 1], a[t >> 1] * xls[t]);
    }
#pragma unroll
    for (int t = 0; t < 8; t++) {
        int c = lane + 32 * t;
        float o = acc[t] / (dn[t >> 1] + 1e-16f) + sbias[c];
        o = (o > 0.f) ? o : expm1f(o);   // ELU
        g_h1[(size_t)d * 256 + c] = o;
    }
}

// ---------------- conv2: EDGE-PAIR unroll, online softmax, fused mean-pool --------------
__device__ __forceinline__ float conv2_logit_reg(float xs0, float xs1, const float (&attr)[8],
                                                 float ebsc, float xr0, float xr1, int lane,
                                                 const float* __restrict__ sEW,
                                                 const float* __restrict__ seb,
                                                 const float* __restrict__ satt) {
    float p = 0.f;
#pragma unroll
    for (int t = 0; t < 2; t++) {
        int c = lane + 32 * t;
        float ep = ebsc * seb[c];
#pragma unroll
        for (int j = 0; j < 8; j++) ep += attr[j] * sEW[j * 64 + c];
        float v = (t == 0 ? xs0 : xs1) + (t == 0 ? xr0 : xr1) + ep;
        float m = v > 0.f ? v : 0.2f * v;
        p += m * satt[c];
    }
#pragma unroll
    for (int off = 16; off > 0; off >>= 1) p += __shfl_xor_sync(0xffffffffu, p, off);
    return p;
}

__global__ void __launch_bounds__(256) k_conv2(const float* __restrict__ att2,
                                               const float* __restrict__ bias2,
                                               const void* __restrict__ batch) {
    __shared__ float sEW[512];
    __shared__ float seb[64];
    __shared__ float satt[64];
    __shared__ float sbias[64];
    int tid = threadIdx.x;
    for (int i = tid; i < 512; i += 256) sEW[i] = g_EW2[i];
    if (tid < 64) { seb[tid] = g_eb2[tid]; satt[tid] = att2[tid]; sbias[tid] = bias2[tid]; }
    __syncthreads();

    int lane = tid & 31;
    int d = blockIdx.x * 8 + (tid >> 5);
    if (d >= NN) return;

    int beg = g_rowptr[d], end = g_rowptr[d + 1];
    float xr0 = g_xr2[(size_t)d * 64 + lane];
    float xr1 = g_xr2[(size_t)d * 64 + lane + 32];

    float mx, dn, acc0, acc1;
    {
        float4 a0 = *reinterpret_cast<const float4*>(&g_loop8[d * 8]);
        float4 a1 = *reinterpret_cast<const float4*>(&g_loop8[d * 8 + 4]);
        float attr[8] = {a0.x, a0.y, a0.z, a0.w, a1.x, a1.y, a1.z, a1.w};
        float xs0 = __ldg(&g_xl2[(size_t)d * 64 + lane]);
        float xs1 = __ldg(&g_xl2[(size_t)d * 64 + lane + 32]);
        mx = conv2_logit_reg(xs0, xs1, attr, g_ebs[d], xr0, xr1, lane, sEW, seb, satt);
        dn = 1.0f; acc0 = xs0; acc1 = xs1;
    }
    int i = beg;
    for (; i + 1 < end; i += 2) {
        int s1 = g_esrc[i], s2 = g_esrc[i + 1];
        float4 a10 = *reinterpret_cast<const float4*>(&g_eatt[(size_t)i * 8]);
        float4 a11 = *reinterpret_cast<const float4*>(&g_eatt[(size_t)i * 8 + 4]);
        float4 a20 = *reinterpret_cast<const float4*>(&g_eatt[(size_t)(i + 1) * 8]);
        float4 a21 = *reinterpret_cast<const float4*>(&g_eatt[(size_t)(i + 1) * 8 + 4]);
        float at1[8] = {a10.x, a10.y, a10.z, a10.w, a11.x, a11.y, a11.z, a11.w};
        float at2[8] = {a20.x, a20.y, a20.z, a20.w, a21.x, a21.y, a21.z, a21.w};
        float x10 = __ldg(&g_xl2[(size_t)s1 * 64 + lane]);
        float x11 = __ldg(&g_xl2[(size_t)s1 * 64 + lane + 32]);
        float x20 = __ldg(&g_xl2[(size_t)s2 * 64 + lane]);
        float x21 = __ldg(&g_xl2[(size_t)s2 * 64 + lane + 32]);
        float p1 = 0.f, p2 = 0.f;
#pragma unroll
        for (int t = 0; t < 2; t++) {
            int c = lane + 32 * t;
            float e1 = seb[c], e2 = e1;
#pragma unroll
            for (int j = 0; j < 8; j++) {
                float w = sEW[j * 64 + c];
                e1 = fmaf(at1[j], w, e1);
                e2 = fmaf(at2[j], w, e2);
            }
            float xrv = (t == 0) ? xr0 : xr1;
            float v1 = e1 + xrv + ((t == 0) ? x10 : x11);
            float v2 = e2 + xrv + ((t == 0) ? x20 : x21);
            v1 = fmaxf(v1, 0.2f * v1);
            v2 = fmaxf(v2, 0.2f * v2);
            float aw = satt[c];
            p1 = fmaf(v1, aw, p1);
            p2 = fmaf(v2, aw, p2);
        }
#pragma unroll
        for (int off = 16; off > 0; off >>= 1) {
            p1 += __shfl_xor_sync(0xffffffffu, p1, off);
            p2 += __shfl_xor_sync(0xffffffffu, p2, off);
        }
        float mnew = fmaxf(mx, fmaxf(p1, p2));
        float c = __expf(mx - mnew);
        float a1 = __expf(p1 - mnew);
        float a2 = __expf(p2 - mnew);
        dn   = fmaf(dn, c, a1 + a2);
        acc0 = fmaf(acc0, c, fmaf(a1, x10, a2 * x20));
        acc1 = fmaf(acc1, c, fmaf(a1, x11, a2 * x21));
        mx = mnew;
    }
    if (i < end) {
        int s = g_esrc[i];
        float4 a0 = *reinterpret_cast<const float4*>(&g_eatt[(size_t)i * 8]);
        float4 a1v = *reinterpret_cast<const float4*>(&g_eatt[(size_t)i * 8 + 4]);
        float attr[8] = {a0.x, a0.y, a0.z, a0.w, a1v.x, a1v.y, a1v.z, a1v.w};
        float xs0 = __ldg(&g_xl2[(size_t)s * 64 + lane]);
        float xs1 = __ldg(&g_xl2[(size_t)s * 64 + lane + 32]);
        float l = conv2_logit_reg(xs0, xs1, attr, 1.0f, xr0, xr1, lane, sEW, seb, satt);
        float mnew = fmaxf(mx, l);
        float c = __expf(mx - mnew);
        float a = __expf(l - mnew);
        dn   = fmaf(dn, c, a);
        acc0 = fmaf(acc0, c, a * xs0);
        acc1 = fmaf(acc1, c, a * xs1);
        mx = mnew;
    }
    float inv = 1.0f / (dn + 1e-16f);
    float o0 = acc0 * inv + sbias[lane];
    float o1 = acc1 * inv + sbias[lane + 32];
    int b = load_idx(batch, d, g_is64);
    b = min(max(b, 0), NB - 1);
    atomicAdd(&g_pool[b * 64 + lane], o0);
    atomicAdd(&g_pool[b * 64 + lane + 32], o1);
}

// ---------------- decoder ------------------------------------------------------------
__global__ void k_decoder(const float* __restrict__ Wd1, const float* __restrict__ bd1,
                          const float* __restrict__ Wd2, const float* __restrict__ bd2,
                          float* __restrict__ out) {
    int b = threadIdx.x;
    if (b >= NB) return;
    float inv = 1.0f / fmaxf(g_cnt[b], 1.0f);
    float p[64];
#pragma unroll
    for (int i = 0; i < 64; i++) p[i] = g_pool[b * 64 + i] * inv;
    float o0 = bd2[0], o1 = bd2[1];
    for (int j = 0; j < 64; j++) {
        float s = bd1[j];
#pragma unroll
        for (int i = 0; i < 64; i++) s += p[i] * Wd1[i * 64 + j];
        s = fmaxf(s, 0.f);
        o0 += s * Wd2[j * 2 + 0];
        o1 += s * Wd2[j * 2 + 1];
    }
    out[b * 2 + 0] = 1.0f / (1.0f + expf(-o0));
    out[b * 2 + 1] = 1.0f / (1.0f + expf(-o1));
}

// ---------------- launch ---------------------------------------------------------------
extern "C" void kernel_launch(void* const* d_in, const int* in_sizes, int n_in,
                              void* d_out, int out_size) {
    const float* x      = (const float*)d_in[0];
    const void*  ei     = d_in[1];
    const float* eattr  = (const float*)d_in[2];
    const void*  batch  = d_in[3];
    const float* W_node = (const float*)d_in[4];
    const float* b_node = (const float*)d_in[5];
    const float* W_edge = (const float*)d_in[6];
    const float* b_edge = (const float*)d_in[7];
    const float* Wl1 = (const float*)d_in[8];
    const float* bl1 = (const float*)d_in[9];
    const float* Wr1 = (const float*)d_in[10];
    const float* br1 = (const float*)d_in[11];
    const float* We1 = (const float*)d_in[12];
    const float* att1 = (const float*)d_in[13];
    const float* bias1 = (const float*)d_in[14];
    const float* Wl2 = (const float*)d_in[15];
    const float* bl2 = (const float*)d_in[16];
    const float* Wr2 = (const float*)d_in[17];
    const float* br2 = (const float*)d_in[18];
    const float* We2 = (const float*)d_in[19];
    const float* att2 = (const float*)d_in[20];
    const float* bias2 = (const float*)d_in[21];
    const float* Wd1 = (const float*)d_in[22];
    const float* bd1 = (const float*)d_in[23];
    const float* Wd2 = (const float*)d_in[24];
    const float* bd2 = (const float*)d_in[25];

    k_init<<<256, 256>>>((const int*)ei);
    k_phase1<<<PH1_B, 256>>>(ei, batch, x, W_node, b_node, W_edge, b_edge, We1, We2);
    k_scan<<<1, 1024>>>();
    k_phase3<<<PH3_B, 256>>>(eattr, Wl1, bl1, Wr1, br1);
    k_loopattr<<<(NN + 7) / 8, 256>>>();
    k_conv1<<<(NN + 7) / 8, 256>>>(att1, bias1);
    k_gemm2b<<<G2X, 256>>>(Wl2, bl2, Wr2, br2);
    k_conv2<<<(NN + 7) / 8, 256>>>(att2, bias2, batch);
    k_decoder<<<1, 64>>>(Wd1, bd1, Wd2, bd2, (float*)d_out);
}

// round 15
// speedup vs baseline: 1.0334x; 1.0334x over previous
#include <cuda_runtime.h>
#include <math.h>

#define NN 50000
#define NE 800000
#define NB 64

#define PREP_B 3125      // (NE+255)/256
#define CNT_B  196       // (NN+255)/256
#define ENC_B  782       // (NN+63)/64
#define PH1_B  (PREP_B + CNT_B + 1 + ENC_B)   // 4104
#define FILL_B 3125
#define G2X    391       // (NN+127)/128
#define PH3_B  (FILL_B + G2X * 4)             // 4689

// ---------------- scratch ---------------------------------------------------------
__device__ int   g_is64;
__device__ int   g_deg[NN];
__device__ int   g_cursor[NN];
__device__ int   g_rowptr[NN + 1];
__device__ int   g_src[NE];
__device__ int   g_dst[NE];
__device__ int   g_esrc[NE];
__device__ __align__(16) float g_eatt[NE * 8];
__device__ __align__(16) float g_loop8[NN * 8];
__device__ float g_ebs[NN];
__device__ __align__(16) float g_h0[NN * 64];
__device__ __align__(16) float g_xl1[NN * 256];
__device__ __align__(16) float g_xr1[NN * 256];
__device__ __align__(16) float g_h1[NN * 256];
__device__ __align__(16) float g_xl2[NN * 64];
__device__ __align__(16) float g_xr2[NN * 64];
__device__ __align__(16) float g_EW1[8 * 256];
__device__ float g_eb1[256];
__device__ __align__(16) float g_EW2[8 * 64];
__device__ float g_eb2[64];
__device__ float g_pool[NB * 64];
__device__ float g_cnt[NB];

__device__ __forceinline__ int load_idx(const void* p, long long i, int is64) {
    if (is64) return (int)((const long long*)p)[i];
    return ((const int*)p)[i];
}

// ---------------- L0: detect dtype + zero accumulators ------------------------------
__global__ void k_init(const int* __restrict__ ei_w) {
    if (blockIdx.x == 0 && threadIdx.x < 32) {
        int v = ei_w[threadIdx.x * 2 + 1];
        unsigned any = __ballot_sync(0xffffffffu, v != 0);
        if (threadIdx.x == 0) g_is64 = (any == 0u) ? 1 : 0;
    }
    int i = blockIdx.x * blockDim.x + threadIdx.x;
    int stride = gridDim.x * blockDim.x;
    for (int t = i; t < NN; t += stride) { g_deg[t] = 0; g_cursor[t] = 0; }
    for (int t = i; t < NB * 64; t += stride) g_pool[t] = 0.f;
    for (int t = i; t < NB; t += stride) g_cnt[t] = 0.f;
}

// ---------------- device pieces for mega-launches ------------------------------------
__device__ void dev_prep(const void* __restrict__ ei, int b) {
    int e = b * 256 + threadIdx.x;
    if (e >= NE) return;
    int is64 = g_is64;
    int s = load_idx(ei, e, is64);
    int d = load_idx(ei, (long long)NE + e, is64);
    s = min(max(s, 0), NN - 1);
    d = min(max(d, 0), NN - 1);
    g_src[e] = s;
    g_dst[e] = d;
    atomicAdd(&g_deg[d], 1);
}

__device__ void dev_cnt(const void* __restrict__ batch, int b) {
    __shared__ int h[NB];
    int tid = threadIdx.x;
    if (tid < NB) h[tid] = 0;
    __syncthreads();
    int n = b * 256 + tid;
    if (n < NN) {
        int bb = load_idx(batch, n, g_is64);
        bb = min(max(bb, 0), NB - 1);
        atomicAdd(&h[bb], 1);
    }
    __syncthreads();
    if (tid < NB && h[tid]) atomicAdd(&g_cnt[tid], (float)h[tid]);
}

__device__ void dev_smallw(const float* __restrict__ W_edge, const float* __restrict__ b_edge,
                           const float* __restrict__ We1, const float* __restrict__ We2) {
    __shared__ float sWe[8 * 64];
    __shared__ float sbe[64];
    int t = threadIdx.x;
    if (t < 64) sbe[t] = b_edge[t];
    for (int i = t; i < 512; i += 256) sWe[i] = W_edge[i];
    __syncthreads();
    {
        float acc[8] = {0, 0, 0, 0, 0, 0, 0, 0};
        float accb = 0.f;
        for (int k = 0; k < 64; k++) {
            float w = We1[k * 256 + t];
            accb += sbe[k] * w;
#pragma unroll
            for (int j = 0; j < 8; j++) acc[j] += sWe[j * 64 + k] * w;
        }
#pragma unroll
        for (int j = 0; j < 8; j++) g_EW1[j * 256 + t] = acc[j];
        g_eb1[t] = accb;
    }
    if (t < 64) {
        float acc[8] = {0, 0, 0, 0, 0, 0, 0, 0};
        float accb = 0.f;
        for (int k = 0; k < 64; k++) {
            float w = We2[k * 64 + t];
            accb += sbe[k] * w;
#pragma unroll
            for (int j = 0; j < 8; j++) acc[j] += sWe[j * 64 + k] * w;
        }
#pragma unroll
        for (int j = 0; j < 8; j++) g_EW2[j * 64 + t] = acc[j];
        g_eb2[t] = accb;
    }
}

// encoder GEMM tile: C[row0:+64, 0:64] = A[.,0:16] @ W + bias
__device__ void dev_gemm_enc(const float* __restrict__ A, const float* __restrict__ W,
                             const float* __restrict__ bias, float* __restrict__ C, int row0) {
    const int K = 16, Cc = 64;
    __shared__ float sA[64][17];
    __shared__ float sW[16][64];
    int tid = threadIdx.x;
    int tx = tid & 15, ty = tid >> 4;
#pragma unroll
    for (int i = tid; i < 1024; i += 256) {
        int r = i >> 4, kk = i & 15;
        int m = row0 + r;
        sA[r][kk] = (m < NN) ? A[(size_t)m * K + kk] : 0.f;
    }
#pragma unroll
    for (int i = tid; i < 1024; i += 256) {
        int kk = i >> 6, c = i & 63;
        sW[kk][c] = W[(size_t)kk * Cc + c];
    }
    __syncthreads();
    float acc[4][4] = {};
#pragma unroll
    for (int kk = 0; kk < 16; kk++) {
        float4 wv = *reinterpret_cast<const float4*>(&sW[kk][tx * 4]);
        float a0 = sA[ty * 4 + 0][kk];
        float a1 = sA[ty * 4 + 1][kk];
        float a2 = sA[ty * 4 + 2][kk];
        float a3 = sA[ty * 4 + 3][kk];
        acc[0][0] += a0 * wv.x; acc[0][1] += a0 * wv.y; acc[0][2] += a0 * wv.z; acc[0][3] += a0 * wv.w;
        acc[1][0] += a1 * wv.x; acc[1][1] += a1 * wv.y; acc[1][2] += a1 * wv.z; acc[1][3] += a1 * wv.w;
        acc[2][0] += a2 * wv.x; acc[2][1] += a2 * wv.y; acc[2][2] += a2 * wv.z; acc[2][3] += a2 * wv.w;
        acc[3][0] += a3 * wv.x; acc[3][1] += a3 * wv.y; acc[3][2] += a3 * wv.z; acc[3][3] += a3 * wv.w;
    }
    float b0 = bias[tx * 4 + 0], b1 = bias[tx * 4 + 1];
    float b2 = bias[tx * 4 + 2], b3 = bias[tx * 4 + 3];
#pragma unroll
    for (int i = 0; i < 4; i++) {
        int m = row0 + ty * 4 + i;
        if (m < NN)
            *reinterpret_cast<float4*>(&C[(size_t)m * Cc + tx * 4]) =
                make_float4(acc[i][0] + b0, acc[i][1] + b1, acc[i][2] + b2, acc[i][3] + b3);
    }
}

// ---------------- L1 mega: prep + cnt + smallw + encoder GEMM ------------------------
__global__ void __launch_bounds__(256) k_phase1(const void* __restrict__ ei,
                                                const void* __restrict__ batch,
                                                const float* __restrict__ x,
                                                const float* __restrict__ W_node,
                                                const float* __restrict__ b_node,
                                                const float* __restrict__ W_edge,
                                                const float* __restrict__ b_edge,
                                                const float* __restrict__ We1,
                                                const float* __restrict__ We2) {
    int b = blockIdx.x;
    if (b < PREP_B)                       dev_prep(ei, b);
    else if (b < PREP_B + CNT_B)          dev_cnt(batch, b - PREP_B);
    else if (b == PREP_B + CNT_B)         dev_smallw(W_edge, b_edge, We1, We2);
    else                                  dev_gemm_enc(x, W_node, b_node, g_h0,
                                                       (b - PREP_B - CNT_B - 1) * 64);
}

// ---------------- L2: exclusive scan deg -> rowptr ------------------------------------
__global__ void k_scan() {
    __shared__ int warpsums[32];
    __shared__ int s_carry;
    int tid = threadIdx.x;
    int lane = tid & 31, wid = tid >> 5;
    if (tid == 0) { g_rowptr[0] = 0; s_carry = 0; }
    __syncthreads();
    for (int base = 0; base < NN; base += 1024) {
        int i = base + tid;
        int v = (i < NN) ? g_deg[i] : 0;
        int x = v;
#pragma unroll
        for (int off = 1; off < 32; off <<= 1) {
            int y = __shfl_up_sync(0xffffffffu, x, off);
            if (lane >= off) x += y;
        }
        if (lane == 31) warpsums[wid] = x;
        __syncthreads();
        if (wid == 0) {
            int w = warpsums[lane];
#pragma unroll
            for (int off = 1; off < 32; off <<= 1) {
                int y = __shfl_up_sync(0xffffffffu, w, off);
                if (lane >= off) w += y;
            }
            warpsums[lane] = w;
        }
        __syncthreads();
        int excl = s_carry + ((wid > 0) ? warpsums[wid - 1] : 0);
        int incl = excl + x;
        if (i < NN) g_rowptr[i + 1] = incl;
        __syncthreads();
        if (tid == 0) s_carry += warpsums[31];
        __syncthreads();
    }
}

// ---------------- dual GEMM tile (128x64, 2 outputs) -----------------------------------
__device__ void dev_gemm2(const float* __restrict__ A,
                          const float* __restrict__ W1, const float* __restrict__ b1,
                          const float* __restrict__ W2, const float* __restrict__ b2,
                          float* __restrict__ C1, float* __restrict__ C2,
                          int K, int Cc, int row0, int col0) {
    __shared__ __align__(16) float sA[16][132];
    __shared__ __align__(16) float sW[2][16][64];
    int tid = threadIdx.x;
    int tx = tid & 15, ty = tid >> 4;

    float acc1[8][4] = {}, acc2[8][4] = {};
    for (int k0 = 0; k0 < K; k0 += 16) {
#pragma unroll
        for (int p = 0; p < 2; p++) {
            int r = p * 64 + (tid >> 2);
            int kv = (tid & 3) * 4;
            int m = row0 + r;
            float4 v = make_float4(0.f, 0.f, 0.f, 0.f);
            if (m < NN) v = *reinterpret_cast<const float4*>(&A[(size_t)m * K + k0 + kv]);
            sA[kv + 0][r] = v.x;
            sA[kv + 1][r] = v.y;
            sA[kv + 2][r] = v.z;
            sA[kv + 3][r] = v.w;
        }
        {
            int kk = tid >> 4, c = (tid & 15) * 4;
            size_t off = (size_t)(k0 + kk) * Cc + col0 + c;
            *reinterpret_cast<float4*>(&sW[0][kk][c]) = *reinterpret_cast<const float4*>(&W1[off]);
            *reinterpret_cast<float4*>(&sW[1][kk][c]) = *reinterpret_cast<const float4*>(&W2[off]);
        }
        __syncthreads();
#pragma unroll
        for (int kk = 0; kk < 16; kk++) {
            float4 a0 = *reinterpret_cast<const float4*>(&sA[kk][ty * 8]);
            float4 a1 = *reinterpret_cast<const float4*>(&sA[kk][ty * 8 + 4]);
            float4 w1 = *reinterpret_cast<const float4*>(&sW[0][kk][tx * 4]);
            float4 w2 = *reinterpret_cast<const float4*>(&sW[1][kk][tx * 4]);
            float ar[8] = {a0.x, a0.y, a0.z, a0.w, a1.x, a1.y, a1.z, a1.w};
#pragma unroll
            for (int r = 0; r < 8; r++) {
                acc1[r][0] = fmaf(ar[r], w1.x, acc1[r][0]);
                acc1[r][1] = fmaf(ar[r], w1.y, acc1[r][1]);
                acc1[r][2] = fmaf(ar[r], w1.z, acc1[r][2]);
                acc1[r][3] = fmaf(ar[r], w1.w, acc1[r][3]);
                acc2[r][0] = fmaf(ar[r], w2.x, acc2[r][0]);
                acc2[r][1] = fmaf(ar[r], w2.y, acc2[r][1]);
                acc2[r][2] = fmaf(ar[r], w2.z, acc2[r][2]);
                acc2[r][3] = fmaf(ar[r], w2.w, acc2[r][3]);
            }
        }
        __syncthreads();
    }
    float b1v0 = b1[col0 + tx * 4 + 0], b1v1 = b1[col0 + tx * 4 + 1];
    float b1v2 = b1[col0 + tx * 4 + 2], b1v3 = b1[col0 + tx * 4 + 3];
    float b2v0 = b2[col0 + tx * 4 + 0], b2v1 = b2[col0 + tx * 4 + 1];
    float b2v2 = b2[col0 + tx * 4 + 2], b2v3 = b2[col0 + tx * 4 + 3];
#pragma unroll
    for (int r = 0; r < 8; r++) {
        int m = row0 + ty * 8 + r;
        if (m < NN) {
            *reinterpret_cast<float4*>(&C1[(size_t)m * Cc + col0 + tx * 4]) =
                make_float4(acc1[r][0] + b1v0, acc1[r][1] + b1v1, acc1[r][2] + b1v2, acc1[r][3] + b1v3);
            *reinterpret_cast<float4*>(&C2[(size_t)m * Cc + col0 + tx * 4]) =
                make_float4(acc2[r][0] + b2v0, acc2[r][1] + b2v1, acc2[r][2] + b2v2, acc2[r][3] + b2v3);
        }
    }
}

__device__ void dev_fill(const float* __restrict__ eattr, int b) {
    int e = b * 256 + threadIdx.x;
    if (e >= NE) return;
    int d = g_dst[e];
    int p = g_rowptr[d] + atomicAdd(&g_cursor[d], 1);
    g_esrc[p] = g_src[e];
    float a[8];
#pragma unroll
    for (int j = 0; j < 8; j++) a[j] = eattr[e * 8 + j];
    reinterpret_cast<float4*>(g_eatt)[p * 2] = make_float4(a[0], a[1], a[2], a[3]);
    reinterpret_cast<float4*>(g_eatt)[p * 2 + 1] = make_float4(a[4], a[5], a[6], a[7]);
}

// ---------------- L3 mega: CSR fill + conv1-transform dual GEMM ------------------------
__global__ void __launch_bounds__(256) k_phase3(const float* __restrict__ eattr,
                                                const float* __restrict__ Wl1,
                                                const float* __restrict__ bl1,
                                                const float* __restrict__ Wr1,
                                                const float* __restrict__ br1) {
    int b = blockIdx.x;
    if (b < FILL_B) { dev_fill(eattr, b); return; }
    int idx = b - FILL_B;
    int bx = idx % G2X, by = idx / G2X;
    dev_gemm2(g_h0, Wl1, bl1, Wr1, br1, g_xl1, g_xr1, 64, 256, bx * 128, by * 64);
}

// ---------------- self-loop mean attrs --------------------------------------------------
__global__ void __launch_bounds__(256) k_loopattr() {
    int lane = threadIdx.x & 31;
    int d = blockIdx.x * 8 + (threadIdx.x >> 5);
    if (d >= NN) return;
    int beg = g_rowptr[d], end = g_rowptr[d + 1];
    float s = 0.f;
    for (int i = beg + (lane >> 3); i < end; i += 4)
        s += g_eatt[(size_t)i * 8 + (lane & 7)];
    s += __shfl_xor_sync(0xffffffffu, s, 8);
    s += __shfl_xor_sync(0xffffffffu, s, 16);
    int dg = end - beg;
    if (lane < 8) g_loop8[d * 8 + lane] = s / (float)max(dg, 1);
    if (lane == 0) g_ebs[d] = (dg > 0) ? 1.0f : 0.0f;
}

// ---------------- L5: conv2-transform dual GEMM ----------------------------------------
__global__ void __launch_bounds__(256) k_gemm2b(const float* __restrict__ Wl2,
                                                const float* __restrict__ bl2,
                                                const float* __restrict__ Wr2,
                                                const float* __restrict__ br2) {
    dev_gemm2(g_h1, Wl2, bl2, Wr2, br2, g_xl2, g_xr2, 256, 64, blockIdx.x * 128, 0);
}

// ---------------- conv1: warp-per-dst, EDGE-PAIR unroll (R13 proven) --------------------
__device__ __forceinline__ void conv1_logits_single(const float (&xls)[8], const float (&attr)[8],
                                                    float ebsc, const float (&xr)[8], int lane,
                                                    const float* __restrict__ sEW,
                                                    const float* __restrict__ seb,
                                                    const float* __restrict__ satt,
                                                    float (&out)[4]) {
    float p[4] = {0.f, 0.f, 0.f, 0.f};
#pragma unroll
    for (int t = 0; t < 8; t++) {
        int c = lane + 32 * t;
        float ep = ebsc * seb[c];
#pragma unroll
        for (int j = 0; j < 8; j++) ep += attr[j] * sEW[j * 256 + c];
        float v = xls[t] + xr[t] + ep;
        float m = v > 0.f ? v : 0.2f * v;
        p[t >> 1] += m * satt[(t >> 1) * 64 + (c & 63)];
    }
#pragma unroll
    for (int h = 0; h < 4; h++) {
#pragma unroll
        for (int off = 16; off > 0; off >>= 1)
            p[h] += __shfl_xor_sync(0xffffffffu, p[h], off);
        out[h] = p[h];
    }
}

__global__ void __launch_bounds__(256) k_conv1(const float* __restrict__ att1,
                                               const float* __restrict__ bias1) {
    __shared__ float sEW[2048];
    __shared__ float seb[256];
    __shared__ float satt[256];
    __shared__ float sbias[256];
    int tid = threadIdx.x;
    for (int i = tid; i < 2048; i += 256) sEW[i] = g_EW1[i];
    seb[tid] = g_eb1[tid];
    satt[tid] = att1[tid];
    sbias[tid] = bias1[tid];
    __syncthreads();

    int lane = tid & 31;
    int d = blockIdx.x * 8 + (tid >> 5);
    if (d >= NN) return;

    int beg = g_rowptr[d], end = g_rowptr[d + 1];

    float xr[8];
#pragma unroll
    for (int t = 0; t < 8; t++) xr[t] = g_xr1[(size_t)d * 256 + lane + 32 * t];

    float mx[4], dn[4], acc[8];
    // self loop initializes the online state
    {
        float xls[8];
        float4 a0 = *reinterpret_cast<const float4*>(&g_loop8[d * 8]);
        float4 a1 = *reinterpret_cast<const float4*>(&g_loop8[d * 8 + 4]);
        float attr[8] = {a0.x, a0.y, a0.z, a0.w, a1.x, a1.y, a1.z, a1.w};
#pragma unroll
        for (int t = 0; t < 8; t++) xls[t] = __ldg(&g_xl1[(size_t)d * 256 + lane + 32 * t]);
        float l[4];
        conv1_logits_single(xls, attr, g_ebs[d], xr, lane, sEW, seb, satt, l);
#pragma unroll
        for (int h = 0; h < 4; h++) { mx[h] = l[h]; dn[h] = 1.0f; }
#pragma unroll
        for (int t = 0; t < 8; t++) acc[t] = xls[t];
    }
    // edge pairs: one sEW read serves two edges -> half the crossbar traffic
    int i = beg;
    for (; i + 1 < end; i += 2) {
        int s1 = g_esrc[i], s2 = g_esrc[i + 1];
        float4 a10 = *reinterpret_cast<const float4*>(&g_eatt[(size_t)i * 8]);
        float4 a11 = *reinterpret_cast<const float4*>(&g_eatt[(size_t)i * 8 + 4]);
        float4 a20 = *reinterpret_cast<const float4*>(&g_eatt[(size_t)(i + 1) * 8]);
        float4 a21 = *reinterpret_cast<const float4*>(&g_eatt[(size_t)(i + 1) * 8 + 4]);
        float at1[8] = {a10.x, a10.y, a10.z, a10.w, a11.x, a11.y, a11.z, a11.w};
        float at2[8] = {a20.x, a20.y, a20.z, a20.w, a21.x, a21.y, a21.z, a21.w};
        float x1[8], x2[8];
#pragma unroll
        for (int t = 0; t < 8; t++) {
            x1[t] = __ldg(&g_xl1[(size_t)s1 * 256 + lane + 32 * t]);
            x2[t] = __ldg(&g_xl1[(size_t)s2 * 256 + lane + 32 * t]);
        }
        float p1[4] = {0.f, 0.f, 0.f, 0.f};
        float p2[4] = {0.f, 0.f, 0.f, 0.f};
#pragma unroll
        for (int t = 0; t < 8; t++) {
            int c = lane + 32 * t;
            float e1 = seb[c], e2 = e1;
#pragma unroll
            for (int j = 0; j < 8; j++) {
                float w = sEW[j * 256 + c];
                e1 = fmaf(at1[j], w, e1);
                e2 = fmaf(at2[j], w, e2);
            }
            float v1 = e1 + xr[t] + x1[t];
            float v2 = e2 + xr[t] + x2[t];
            v1 = fmaxf(v1, 0.2f * v1);
            v2 = fmaxf(v2, 0.2f * v2);
            float aw = satt[(t >> 1) * 64 + (c & 63)];
            p1[t >> 1] = fmaf(v1, aw, p1[t >> 1]);
            p2[t >> 1] = fmaf(v2, aw, p2[t >> 1]);
        }
#pragma unroll
        for (int h = 0; h < 4; h++) {
#pragma unroll
            for (int off = 16; off > 0; off >>= 1) {
                p1[h] += __shfl_xor_sync(0xffffffffu, p1[h], off);
                p2[h] += __shfl_xor_sync(0xffffffffu, p2[h], off);
            }
        }
        // fused pair online update (one rescale for both edges)
        float a1h[4], a2h[4], mul[4];
#pragma unroll
        for (int h = 0; h < 4; h++) {
            float mnew = fmaxf(mx[h], fmaxf(p1[h], p2[h]));
            mul[h] = __expf(mx[h] - mnew);
            a1h[h] = __expf(p1[h] - mnew);
            a2h[h] = __expf(p2[h] - mnew);
            dn[h] = fmaf(dn[h], mul[h], a1h[h] + a2h[h]);
            mx[h] = mnew;
        }
#pragma unroll
        for (int t = 0; t < 8; t++)
            acc[t] = fmaf(acc[t], mul[t >> 1], fmaf(a1h[t >> 1], x1[t], a2h[t >> 1] * x2[t]));
    }
    // tail edge (if odd count)
    if (i < end) {
        int s = g_esrc[i];
        float4 a0 = *reinterpret_cast<const float4*>(&g_eatt[(size_t)i * 8]);
        float4 a1 = *reinterpret_cast<const float4*>(&g_eatt[(size_t)i * 8 + 4]);
        float attr[8] = {a0.x, a0.y, a0.z, a0.w, a1.x, a1.y, a1.z, a1.w};
        float xls[8];
#pragma unroll
        for (int t = 0; t < 8; t++) xls[t] = __ldg(&g_xl1[(size_t)s * 256 + lane + 32 * t]);
        float l[4];
        conv1_logits_single(xls, attr, 1.0f, xr, lane, sEW, seb, satt, l);
        float a[4], mul[4];
#pragma unroll
        for (int h = 0; h < 4; h++) {
            float mnew = fmaxf(mx[h], l[h]);
            mul[h] = __expf(mx[h] - mnew);
            a[h]   = __expf(l[h] - mnew);
            dn[h]  = fmaf(dn[h], mul[h], a[h]);
            mx[h]  = mnew;
        }
#pragma unroll
        for (int t = 0; t < 8; t++) acc[t] = fmaf(acc[t], mul[t >> 1], a[t >> 1] * xls[t]);
    }
#pragma unroll
    for (int t = 0; t < 8; t++) {
        int c = lane + 32 * t;
        float o = acc[t] / (dn[t >> 1] + 1e-16f) + sbias[c];
        o = (o > 0.f) ? o : expm1f(o);   // ELU
        g_h1[(size_t)d * 256 + c] = o;
    }
}

// ---------------- conv2: EDGE-QUAD unroll, online softmax, fused mean-pool --------------
__device__ __forceinline__ float conv2_logit_reg(float xs0, float xs1, const float (&attr)[8],
                                                 float ebsc, float xr0, float xr1, int lane,
                                                 const float* __restrict__ sEW,
                                                 const float* __restrict__ seb,
                                                 const float* __restrict__ satt) {
    float p = 0.f;
#pragma unroll
    for (int t = 0; t < 2; t++) {
        int c = lane + 32 * t;
        float ep = ebsc * seb[c];
#pragma unroll
        for (int j = 0; j < 8; j++) ep += attr[j] * sEW[j * 64 + c];
        float v = (t == 0 ? xs0 : xs1) + (t == 0 ? xr0 : xr1) + ep;
        float m = v > 0.f ? v : 0.2f * v;
        p += m * satt[c];
    }
#pragma unroll
    for (int off = 16; off > 0; off >>= 1) p += __shfl_xor_sync(0xffffffffu, p, off);
    return p;
}

__global__ void __launch_bounds__(256) k_conv2(const float* __restrict__ att2,
                                               const float* __restrict__ bias2,
                                               const void* __restrict__ batch) {
    __shared__ float sEW[512];
    __shared__ float seb[64];
    __shared__ float satt[64];
    __shared__ float sbias[64];
    int tid = threadIdx.x;
    for (int i = tid; i < 512; i += 256) sEW[i] = g_EW2[i];
    if (tid < 64) { seb[tid] = g_eb2[tid]; satt[tid] = att2[tid]; sbias[tid] = bias2[tid]; }
    __syncthreads();

    int lane = tid & 31;
    int d = blockIdx.x * 8 + (tid >> 5);
    if (d >= NN) return;

    int beg = g_rowptr[d], end = g_rowptr[d + 1];
    float xr0 = g_xr2[(size_t)d * 64 + lane];
    float xr1 = g_xr2[(size_t)d * 64 + lane + 32];

    float mx, dn, acc0, acc1;
    {
        float4 a0 = *reinterpret_cast<const float4*>(&g_loop8[d * 8]);
        float4 a1 = *reinterpret_cast<const float4*>(&g_loop8[d * 8 + 4]);
        float attr[8] = {a0.x, a0.y, a0.z, a0.w, a1.x, a1.y, a1.z, a1.w};
        float xs0 = __ldg(&g_xl2[(size_t)d * 64 + lane]);
        float xs1 = __ldg(&g_xl2[(size_t)d * 64 + lane + 32]);
        mx = conv2_logit_reg(xs0, xs1, attr, g_ebs[d], xr0, xr1, lane, sEW, seb, satt);
        dn = 1.0f; acc0 = xs0; acc1 = xs1;
    }
    int i = beg;
    // edge QUADS: one sEW read serves four edges
    for (; i + 3 < end; i += 4) {
        int s1 = g_esrc[i], s2 = g_esrc[i + 1], s3 = g_esrc[i + 2], s4 = g_esrc[i + 3];
        float4 a10 = *reinterpret_cast<const float4*>(&g_eatt[(size_t)i * 8]);
        float4 a11 = *reinterpret_cast<const float4*>(&g_eatt[(size_t)i * 8 + 4]);
        float4 a20 = *reinterpret_cast<const float4*>(&g_eatt[(size_t)(i + 1) * 8]);
        float4 a21 = *reinterpret_cast<const float4*>(&g_eatt[(size_t)(i + 1) * 8 + 4]);
        float4 a30 = *reinterpret_cast<const float4*>(&g_eatt[(size_t)(i + 2) * 8]);
        float4 a31 = *reinterpret_cast<const float4*>(&g_eatt[(size_t)(i + 2) * 8 + 4]);
        float4 a40 = *reinterpret_cast<const float4*>(&g_eatt[(size_t)(i + 3) * 8]);
        float4 a41 = *reinterpret_cast<const float4*>(&g_eatt[(size_t)(i + 3) * 8 + 4]);
        float at1[8] = {a10.x, a10.y, a10.z, a10.w, a11.x, a11.y, a11.z, a11.w};
        float at2[8] = {a20.x, a20.y, a20.z, a20.w, a21.x, a21.y, a21.z, a21.w};
        float at3[8] = {a30.x, a30.y, a30.z, a30.w, a31.x, a31.y, a31.z, a31.w};
        float at4[8] = {a40.x, a40.y, a40.z, a40.w, a41.x, a41.y, a41.z, a41.w};
        float x10 = __ldg(&g_xl2[(size_t)s1 * 64 + lane]);
        float x11 = __ldg(&g_xl2[(size_t)s1 * 64 + lane + 32]);
        float x20 = __ldg(&g_xl2[(size_t)s2 * 64 + lane]);
        float x21 = __ldg(&g_xl2[(size_t)s2 * 64 + lane + 32]);
        float x30 = __ldg(&g_xl2[(size_t)s3 * 64 + lane]);
        float x31 = __ldg(&g_xl2[(size_t)s3 * 64 + lane + 32]);
        float x40 = __ldg(&g_xl2[(size_t)s4 * 64 + lane]);
        float x41 = __ldg(&g_xl2[(size_t)s4 * 64 + lane + 32]);
        float p1 = 0.f, p2 = 0.f, p3 = 0.f, p4 = 0.f;
#pragma unroll
        for (int t = 0; t < 2; t++) {
            int c = lane + 32 * t;
            float eb = seb[c];
            float e1 = eb, e2 = eb, e3 = eb, e4 = eb;
#pragma unroll
            for (int j = 0; j < 8; j++) {
                float w = sEW[j * 64 + c];
                e1 = fmaf(at1[j], w, e1);
                e2 = fmaf(at2[j], w, e2);
                e3 = fmaf(at3[j], w, e3);
                e4 = fmaf(at4[j], w, e4);
            }
            float xrv = (t == 0) ? xr0 : xr1;
            float v1 = e1 + xrv + ((t == 0) ? x10 : x11);
            float v2 = e2 + xrv + ((t == 0) ? x20 : x21);
            float v3 = e3 + xrv + ((t == 0) ? x30 : x31);
            float v4 = e4 + xrv + ((t == 0) ? x40 : x41);
            v1 = fmaxf(v1, 0.2f * v1);
            v2 = fmaxf(v2, 0.2f * v2);
            v3 = fmaxf(v3, 0.2f * v3);
            v4 = fmaxf(v4, 0.2f * v4);
            float aw = satt[c];
            p1 = fmaf(v1, aw, p1);
            p2 = fmaf(v2, aw, p2);
            p3 = fmaf(v3, aw, p3);
            p4 = fmaf(v4, aw, p4);
        }
#pragma unroll
        for (int off = 16; off > 0; off >>= 1) {
            p1 += __shfl_xor_sync(0xffffffffu, p1, off);
            p2 += __shfl_xor_sync(0xffffffffu, p2, off);
            p3 += __shfl_xor_sync(0xffffffffu, p3, off);
            p4 += __shfl_xor_sync(0xffffffffu, p4, off);
        }
        float mnew = fmaxf(fmaxf(mx, fmaxf(p1, p2)), fmaxf(p3, p4));
        float c  = __expf(mx - mnew);
        float a1 = __expf(p1 - mnew);
        float a2 = __expf(p2 - mnew);
        float a3 = __expf(p3 - mnew);
        float a4 = __expf(p4 - mnew);
        dn   = fmaf(dn, c, (a1 + a2) + (a3 + a4));
        float add0 = fmaf(a1, x10, a2 * x20); add0 = fmaf(a3, x30, add0); add0 = fmaf(a4, x40, add0);
        float add1 = fmaf(a1, x11, a2 * x21); add1 = fmaf(a3, x31, add1); add1 = fmaf(a4, x41, add1);
        acc0 = fmaf(acc0, c, add0);
        acc1 = fmaf(acc1, c, add1);
        mx = mnew;
    }
    // pair tail
    for (; i + 1 < end; i += 2) {
        int s1 = g_esrc[i], s2 = g_esrc[i + 1];
        float4 a10 = *reinterpret_cast<const float4*>(&g_eatt[(size_t)i * 8]);
        float4 a11 = *reinterpret_cast<const float4*>(&g_eatt[(size_t)i * 8 + 4]);
        float4 a20 = *reinterpret_cast<const float4*>(&g_eatt[(size_t)(i + 1) * 8]);
        float4 a21 = *reinterpret_cast<const float4*>(&g_eatt[(size_t)(i + 1) * 8 + 4]);
        float at1[8] = {a10.x, a10.y, a10.z, a10.w, a11.x, a11.y, a11.z, a11.w};
        float at2[8] = {a20.x, a20.y, a20.z, a20.w, a21.x, a21.y, a21.z, a21.w};
        float x10 = __ldg(&g_xl2[(size_t)s1 * 64 + lane]);
        float x11 = __ldg(&g_xl2[(size_t)s1 * 64 + lane + 32]);
        float x20 = __ldg(&g_xl2[(size_t)s2 * 64 + lane]);
        float x21 = __ldg(&g_xl2[(size_t)s2 * 64 + lane + 32]);
        float p1 = 0.f, p2 = 0.f;
#pragma unroll
        for (int t = 0; t < 2; t++) {
            int c = lane + 32 * t;
            float e1 = seb[c], e2 = e1;
#pragma unroll
            for (int j = 0; j < 8; j++) {
                float w = sEW[j * 64 + c];
                e1 = fmaf(at1[j], w, e1);
                e2 = fmaf(at2[j], w, e2);
            }
            float xrv = (t == 0) ? xr0 : xr1;
            float v1 = e1 + xrv + ((t == 0) ? x10 : x11);
            float v2 = e2 + xrv + ((t == 0) ? x20 : x21);
            v1 = fmaxf(v1, 0.2f * v1);
            v2 = fmaxf(v2, 0.2f * v2);
            float aw = satt[c];
            p1 = fmaf(v1, aw, p1);
            p2 = fmaf(v2, aw, p2);
        }
#pragma unroll
        for (int off = 16; off > 0; off >>= 1) {
            p1 += __shfl_xor_sync(0xffffffffu, p1, off);
            p2 += __shfl_xor_sync(0xffffffffu, p2, off);
        }
        float mnew = fmaxf(mx, fmaxf(p1, p2));
        float c = __expf(mx - mnew);
        float a1 = __expf(p1 - mnew);
        float a2 = __expf(p2 - mnew);
        dn   = fmaf(dn, c, a1 + a2);
        acc0 = fmaf(acc0, c, fmaf(a1, x10, a2 * x20));
        acc1 = fmaf(acc1, c, fmaf(a1, x11, a2 * x21));
        mx = mnew;
    }
    // single tail
    if (i < end) {
        int s = g_esrc[i];
        float4 a0 = *reinterpret_cast<const float4*>(&g_eatt[(size_t)i * 8]);
        float4 a1v = *reinterpret_cast<const float4*>(&g_eatt[(size_t)i * 8 + 4]);
        float attr[8] = {a0.x, a0.y, a0.z, a0.w, a1v.x, a1v.y, a1v.z, a1v.w};
        float xs0 = __ldg(&g_xl2[(size_t)s * 64 + lane]);
        float xs1 = __ldg(&g_xl2[(size_t)s * 64 + lane + 32]);
        float l = conv2_logit_reg(xs0, xs1, attr, 1.0f, xr0, xr1, lane, sEW, seb, satt);
        float mnew = fmaxf(mx, l);
        float c = __expf(mx - mnew);
        float a = __expf(l - mnew);
        dn   = fmaf(dn, c, a);
        acc0 = fmaf(acc0, c, a * xs0);
        acc1 = fmaf(acc1, c, a * xs1);
        mx = mnew;
    }
    float inv = 1.0f / (dn + 1e-16f);
    float o0 = acc0 * inv + sbias[lane];
    float o1 = acc1 * inv + sbias[lane + 32];
    int b = load_idx(batch, d, g_is64);
    b = min(max(b, 0), NB - 1);
    atomicAdd(&g_pool[b * 64 + lane], o0);
    atomicAdd(&g_pool[b * 64 + lane + 32], o1);
}

// ---------------- decoder ------------------------------------------------------------
__global__ void k_decoder(const float* __restrict__ Wd1, const float* __restrict__ bd1,
                          const float* __restrict__ Wd2, const float* __restrict__ bd2,
                          float* __restrict__ out) {
    int b = threadIdx.x;
    if (b >= NB) return;
    float inv = 1.0f / fmaxf(g_cnt[b], 1.0f);
    float p[64];
#pragma unroll
    for (int i = 0; i < 64; i++) p[i] = g_pool[b * 64 + i] * inv;
    float o0 = bd2[0], o1 = bd2[1];
    for (int j = 0; j < 64; j++) {
        float s = bd1[j];
#pragma unroll
        for (int i = 0; i < 64; i++) s += p[i] * Wd1[i * 64 + j];
        s = fmaxf(s, 0.f);
        o0 += s * Wd2[j * 2 + 0];
        o1 += s * Wd2[j * 2 + 1];
    }
    out[b * 2 + 0] = 1.0f / (1.0f + expf(-o0));
    out[b * 2 + 1] = 1.0f / (1.0f + expf(-o1));
}

// ---------------- launch ---------------------------------------------------------------
extern "C" void kernel_launch(void* const* d_in, const int* in_sizes, int n_in,
                              void* d_out, int out_size) {
    const float* x      = (const float*)d_in[0];
    const void*  ei     = d_in[1];
    const float* eattr  = (const float*)d_in[2];
    const void*  batch  = d_in[3];
    const float* W_node = (const float*)d_in[4];
    const float* b_node = (const float*)d_in[5];
    const float* W_edge = (const float*)d_in[6];
    const float* b_edge = (const float*)d_in[7];
    const float* Wl1 = (const float*)d_in[8];
    const float* bl1 = (const float*)d_in[9];
    const float* Wr1 = (const float*)d_in[10];
    const float* br1 = (const float*)d_in[11];
    const float* We1 = (const float*)d_in[12];
    const float* att1 = (const float*)d_in[13];
    const float* bias1 = (const float*)d_in[14];
    const float* Wl2 = (const float*)d_in[15];
    const float* bl2 = (const float*)d_in[16];
    const float* Wr2 = (const float*)d_in[17];
    const float* br2 = (const float*)d_in[18];
    const float* We2 = (const float*)d_in[19];
    const float* att2 = (const float*)d_in[20];
    const float* bias2 = (const float*)d_in[21];
    const float* Wd1 = (const float*)d_in[22];
    const float* bd1 = (const float*)d_in[23];
    const float* Wd2 = (const float*)d_in[24];
    const float* bd2 = (const float*)d_in[25];

    k_init<<<256, 256>>>((const int*)ei);
    k_phase1<<<PH1_B, 256>>>(ei, batch, x, W_node, b_node, W_edge, b_edge, We1, We2);
    k_scan<<<1, 1024>>>();
    k_phase3<<<PH3_B, 256>>>(eattr, Wl1, bl1, Wr1, br1);
    k_loopattr<<<(NN + 7) / 8, 256>>>();
    k_conv1<<<(NN + 7) / 8, 256>>>(att1, bias1);
    k_gemm2b<<<G2X, 256>>>(Wl2, bl2, Wr2, br2);
    k_conv2<<<(NN + 7) / 8, 256>>>(att2, bias2, batch);
    k_decoder<<<1, 64>>>(Wd1, bd1, Wd2, bd2, (float*)d_out);
}

// round 16
// speedup vs baseline: 1.0406x; 1.0069x over previous
#include <cuda_runtime.h>
#include <math.h>

#define NN 50000
#define NE 800000
#define NB 64

#define PREP_B 3125      // (NE+255)/256
#define CNT_B  196       // (NN+255)/256
#define ENC_B  782       // (NN+63)/64
#define PH1_B  (PREP_B + CNT_B + 1 + ENC_B)   // 4104
#define FILL_B 3125
#define G2X    391       // (NN+127)/128
#define PH3_B  (FILL_B + G2X * 4)             // 4689

// ---------------- scratch ---------------------------------------------------------
__device__ int   g_is64;
__device__ int   g_deg[NN];
__device__ int   g_cursor[NN];
__device__ int   g_rowptr[NN + 1];
__device__ int   g_src[NE];
__device__ int   g_dst[NE];
__device__ int   g_esrc[NE];
__device__ __align__(16) float g_eatt[NE * 8];
__device__ __align__(16) float g_loop8[NN * 8];
__device__ float g_ebs[NN];
__device__ __align__(16) float g_h0[NN * 64];
__device__ __align__(16) float g_xl1[NN * 256];
__device__ __align__(16) float g_xr1[NN * 256];
__device__ __align__(16) float g_h1[NN * 256];
__device__ __align__(16) float g_xl2[NN * 64];
__device__ __align__(16) float g_xr2[NN * 64];
__device__ __align__(16) float g_EW1[8 * 256];
__device__ float g_eb1[256];
__device__ __align__(16) float g_EW2[8 * 64];
__device__ float g_eb2[64];
__device__ float g_pool[NB * 64];
__device__ float g_cnt[NB];

__device__ __forceinline__ int load_idx(const void* p, long long i, int is64) {
    if (is64) return (int)((const long long*)p)[i];
    return ((const int*)p)[i];
}

// ---------------- L0: detect dtype + zero accumulators ------------------------------
__global__ void k_init(const int* __restrict__ ei_w) {
    if (blockIdx.x == 0 && threadIdx.x < 32) {
        int v = ei_w[threadIdx.x * 2 + 1];
        unsigned any = __ballot_sync(0xffffffffu, v != 0);
        if (threadIdx.x == 0) g_is64 = (any == 0u) ? 1 : 0;
    }
    int i = blockIdx.x * blockDim.x + threadIdx.x;
    int stride = gridDim.x * blockDim.x;
    for (int t = i; t < NN; t += stride) { g_deg[t] = 0; g_cursor[t] = 0; }
    for (int t = i; t < NB * 64; t += stride) g_pool[t] = 0.f;
    for (int t = i; t < NB; t += stride) g_cnt[t] = 0.f;
}

// ---------------- device pieces for mega-launches ------------------------------------
__device__ void dev_prep(const void* __restrict__ ei, int b) {
    int e = b * 256 + threadIdx.x;
    if (e >= NE) return;
    int is64 = g_is64;
    int s = load_idx(ei, e, is64);
    int d = load_idx(ei, (long long)NE + e, is64);
    s = min(max(s, 0), NN - 1);
    d = min(max(d, 0), NN - 1);
    g_src[e] = s;
    g_dst[e] = d;
    atomicAdd(&g_deg[d], 1);
}

__device__ void dev_cnt(const void* __restrict__ batch, int b) {
    __shared__ int h[NB];
    int tid = threadIdx.x;
    if (tid < NB) h[tid] = 0;
    __syncthreads();
    int n = b * 256 + tid;
    if (n < NN) {
        int bb = load_idx(batch, n, g_is64);
        bb = min(max(bb, 0), NB - 1);
        atomicAdd(&h[bb], 1);
    }
    __syncthreads();
    if (tid < NB && h[tid]) atomicAdd(&g_cnt[tid], (float)h[tid]);
}

__device__ void dev_smallw(const float* __restrict__ W_edge, const float* __restrict__ b_edge,
                           const float* __restrict__ We1, const float* __restrict__ We2) {
    __shared__ float sWe[8 * 64];
    __shared__ float sbe[64];
    int t = threadIdx.x;
    if (t < 64) sbe[t] = b_edge[t];
    for (int i = t; i < 512; i += 256) sWe[i] = W_edge[i];
    __syncthreads();
    {
        float acc[8] = {0, 0, 0, 0, 0, 0, 0, 0};
        float accb = 0.f;
        for (int k = 0; k < 64; k++) {
            float w = We1[k * 256 + t];
            accb += sbe[k] * w;
#pragma unroll
            for (int j = 0; j < 8; j++) acc[j] += sWe[j * 64 + k] * w;
        }
#pragma unroll
        for (int j = 0; j < 8; j++) g_EW1[j * 256 + t] = acc[j];
        g_eb1[t] = accb;
    }
    if (t < 64) {
        float acc[8] = {0, 0, 0, 0, 0, 0, 0, 0};
        float accb = 0.f;
        for (int k = 0; k < 64; k++) {
            float w = We2[k * 64 + t];
            accb += sbe[k] * w;
#pragma unroll
            for (int j = 0; j < 8; j++) acc[j] += sWe[j * 64 + k] * w;
        }
#pragma unroll
        for (int j = 0; j < 8; j++) g_EW2[j * 64 + t] = acc[j];
        g_eb2[t] = accb;
    }
}

// encoder GEMM tile: C[row0:+64, 0:64] = A[.,0:16] @ W + bias
__device__ void dev_gemm_enc(const float* __restrict__ A, const float* __restrict__ W,
                             const float* __restrict__ bias, float* __restrict__ C, int row0) {
    const int K = 16, Cc = 64;
    __shared__ float sA[64][17];
    __shared__ float sW[16][64];
    int tid = threadIdx.x;
    int tx = tid & 15, ty = tid >> 4;
#pragma unroll
    for (int i = tid; i < 1024; i += 256) {
        int r = i >> 4, kk = i & 15;
        int m = row0 + r;
        sA[r][kk] = (m < NN) ? A[(size_t)m * K + kk] : 0.f;
    }
#pragma unroll
    for (int i = tid; i < 1024; i += 256) {
        int kk = i >> 6, c = i & 63;
        sW[kk][c] = W[(size_t)kk * Cc + c];
    }
    __syncthreads();
    float acc[4][4] = {};
#pragma unroll
    for (int kk = 0; kk < 16; kk++) {
        float4 wv = *reinterpret_cast<const float4*>(&sW[kk][tx * 4]);
        float a0 = sA[ty * 4 + 0][kk];
        float a1 = sA[ty * 4 + 1][kk];
        float a2 = sA[ty * 4 + 2][kk];
        float a3 = sA[ty * 4 + 3][kk];
        acc[0][0] += a0 * wv.x; acc[0][1] += a0 * wv.y; acc[0][2] += a0 * wv.z; acc[0][3] += a0 * wv.w;
        acc[1][0] += a1 * wv.x; acc[1][1] += a1 * wv.y; acc[1][2] += a1 * wv.z; acc[1][3] += a1 * wv.w;
        acc[2][0] += a2 * wv.x; acc[2][1] += a2 * wv.y; acc[2][2] += a2 * wv.z; acc[2][3] += a2 * wv.w;
        acc[3][0] += a3 * wv.x; acc[3][1] += a3 * wv.y; acc[3][2] += a3 * wv.z; acc[3][3] += a3 * wv.w;
    }
    float b0 = bias[tx * 4 + 0], b1 = bias[tx * 4 + 1];
    float b2 = bias[tx * 4 + 2], b3 = bias[tx * 4 + 3];
#pragma unroll
    for (int i = 0; i < 4; i++) {
        int m = row0 + ty * 4 + i;
        if (m < NN)
            *reinterpret_cast<float4*>(&C[(size_t)m * Cc + tx * 4]) =
                make_float4(acc[i][0] + b0, acc[i][1] + b1, acc[i][2] + b2, acc[i][3] + b3);
    }
}

// ---------------- L1 mega: prep + cnt + smallw + encoder GEMM ------------------------
__global__ void __launch_bounds__(256) k_phase1(const void* __restrict__ ei,
                                                const void* __restrict__ batch,
                                                const float* __restrict__ x,
                                                const float* __restrict__ W_node,
                                                const float* __restrict__ b_node,
                                                const float* __restrict__ W_edge,
                                                const float* __restrict__ b_edge,
                                                const float* __restrict__ We1,
                                                const float* __restrict__ We2) {
    int b = blockIdx.x;
    if (b < PREP_B)                       dev_prep(ei, b);
    else if (b < PREP_B + CNT_B)          dev_cnt(batch, b - PREP_B);
    else if (b == PREP_B + CNT_B)         dev_smallw(W_edge, b_edge, We1, We2);
    else                                  dev_gemm_enc(x, W_node, b_node, g_h0,
                                                       (b - PREP_B - CNT_B - 1) * 64);
}

// ---------------- L2: exclusive scan deg -> rowptr ------------------------------------
__global__ void k_scan() {
    __shared__ int warpsums[32];
    __shared__ int s_carry;
    int tid = threadIdx.x;
    int lane = tid & 31, wid = tid >> 5;
    if (tid == 0) { g_rowptr[0] = 0; s_carry = 0; }
    __syncthreads();
    for (int base = 0; base < NN; base += 1024) {
        int i = base + tid;
        int v = (i < NN) ? g_deg[i] : 0;
        int x = v;
#pragma unroll
        for (int off = 1; off < 32; off <<= 1) {
            int y = __shfl_up_sync(0xffffffffu, x, off);
            if (lane >= off) x += y;
        }
        if (lane == 31) warpsums[wid] = x;
        __syncthreads();
        if (wid == 0) {
            int w = warpsums[lane];
#pragma unroll
            for (int off = 1; off < 32; off <<= 1) {
                int y = __shfl_up_sync(0xffffffffu, w, off);
                if (lane >= off) w += y;
            }
            warpsums[lane] = w;
        }
        __syncthreads();
        int excl = s_carry + ((wid > 0) ? warpsums[wid - 1] : 0);
        int incl = excl + x;
        if (i < NN) g_rowptr[i + 1] = incl;
        __syncthreads();
        if (tid == 0) s_carry += warpsums[31];
        __syncthreads();
    }
}

// ---------------- dual GEMM tile (128x64, 2 outputs) -----------------------------------
__device__ void dev_gemm2(const float* __restrict__ A,
                          const float* __restrict__ W1, const float* __restrict__ b1,
                          const float* __restrict__ W2, const float* __restrict__ b2,
                          float* __restrict__ C1, float* __restrict__ C2,
                          int K, int Cc, int row0, int col0) {
    __shared__ __align__(16) float sA[16][132];
    __shared__ __align__(16) float sW[2][16][64];
    int tid = threadIdx.x;
    int tx = tid & 15, ty = tid >> 4;

    float acc1[8][4] = {}, acc2[8][4] = {};
    for (int k0 = 0; k0 < K; k0 += 16) {
#pragma unroll
        for (int p = 0; p < 2; p++) {
            int r = p * 64 + (tid >> 2);
            int kv = (tid & 3) * 4;
            int m = row0 + r;
            float4 v = make_float4(0.f, 0.f, 0.f, 0.f);
            if (m < NN) v = *reinterpret_cast<const float4*>(&A[(size_t)m * K + k0 + kv]);
            sA[kv + 0][r] = v.x;
            sA[kv + 1][r] = v.y;
            sA[kv + 2][r] = v.z;
            sA[kv + 3][r] = v.w;
        }
        {
            int kk = tid >> 4, c = (tid & 15) * 4;
            size_t off = (size_t)(k0 + kk) * Cc + col0 + c;
            *reinterpret_cast<float4*>(&sW[0][kk][c]) = *reinterpret_cast<const float4*>(&W1[off]);
            *reinterpret_cast<float4*>(&sW[1][kk][c]) = *reinterpret_cast<const float4*>(&W2[off]);
        }
        __syncthreads();
#pragma unroll
        for (int kk = 0; kk < 16; kk++) {
            float4 a0 = *reinterpret_cast<const float4*>(&sA[kk][ty * 8]);
            float4 a1 = *reinterpret_cast<const float4*>(&sA[kk][ty * 8 + 4]);
            float4 w1 = *reinterpret_cast<const float4*>(&sW[0][kk][tx * 4]);
            float4 w2 = *reinterpret_cast<const float4*>(&sW[1][kk][tx * 4]);
            float ar[8] = {a0.x, a0.y, a0.z, a0.w, a1.x, a1.y, a1.z, a1.w};
#pragma unroll
            for (int r = 0; r < 8; r++) {
                acc1[r][0] = fmaf(ar[r], w1.x, acc1[r][0]);
                acc1[r][1] = fmaf(ar[r], w1.y, acc1[r][1]);
                acc1[r][2] = fmaf(ar[r], w1.z, acc1[r][2]);
                acc1[r][3] = fmaf(ar[r], w1.w, acc1[r][3]);
                acc2[r][0] = fmaf(ar[r], w2.x, acc2[r][0]);
                acc2[r][1] = fmaf(ar[r], w2.y, acc2[r][1]);
                acc2[r][2] = fmaf(ar[r], w2.z, acc2[r][2]);
                acc2[r][3] = fmaf(ar[r], w2.w, acc2[r][3]);
            }
        }
        __syncthreads();
    }
    float b1v0 = b1[col0 + tx * 4 + 0], b1v1 = b1[col0 + tx * 4 + 1];
    float b1v2 = b1[col0 + tx * 4 + 2], b1v3 = b1[col0 + tx * 4 + 3];
    float b2v0 = b2[col0 + tx * 4 + 0], b2v1 = b2[col0 + tx * 4 + 1];
    float b2v2 = b2[col0 + tx * 4 + 2], b2v3 = b2[col0 + tx * 4 + 3];
#pragma unroll
    for (int r = 0; r < 8; r++) {
        int m = row0 + ty * 8 + r;
        if (m < NN) {
            *reinterpret_cast<float4*>(&C1[(size_t)m * Cc + col0 + tx * 4]) =
                make_float4(acc1[r][0] + b1v0, acc1[r][1] + b1v1, acc1[r][2] + b1v2, acc1[r][3] + b1v3);
            *reinterpret_cast<float4*>(&C2[(size_t)m * Cc + col0 + tx * 4]) =
                make_float4(acc2[r][0] + b2v0, acc2[r][1] + b2v1, acc2[r][2] + b2v2, acc2[r][3] + b2v3);
        }
    }
}

__device__ void dev_fill(const float* __restrict__ eattr, int b) {
    int e = b * 256 + threadIdx.x;
    if (e >= NE) return;
    int d = g_dst[e];
    int p = g_rowptr[d] + atomicAdd(&g_cursor[d], 1);
    g_esrc[p] = g_src[e];
    float a[8];
#pragma unroll
    for (int j = 0; j < 8; j++) a[j] = eattr[e * 8 + j];
    reinterpret_cast<float4*>(g_eatt)[p * 2] = make_float4(a[0], a[1], a[2], a[3]);
    reinterpret_cast<float4*>(g_eatt)[p * 2 + 1] = make_float4(a[4], a[5], a[6], a[7]);
}

// ---------------- L3 mega: CSR fill + conv1-transform dual GEMM ------------------------
__global__ void __launch_bounds__(256) k_phase3(const float* __restrict__ eattr,
                                                const float* __restrict__ Wl1,
                                                const float* __restrict__ bl1,
                                                const float* __restrict__ Wr1,
                                                const float* __restrict__ br1) {
    int b = blockIdx.x;
    if (b < FILL_B) { dev_fill(eattr, b); return; }
    int idx = b - FILL_B;
    int bx = idx % G2X, by = idx / G2X;
    dev_gemm2(g_h0, Wl1, bl1, Wr1, br1, g_xl1, g_xr1, 64, 256, bx * 128, by * 64);
}

// ---------------- self-loop mean attrs --------------------------------------------------
__global__ void __launch_bounds__(256) k_loopattr() {
    int lane = threadIdx.x & 31;
    int d = blockIdx.x * 8 + (threadIdx.x >> 5);
    if (d >= NN) return;
    int beg = g_rowptr[d], end = g_rowptr[d + 1];
    float s = 0.f;
    for (int i = beg + (lane >> 3); i < end; i += 4)
        s += g_eatt[(size_t)i * 8 + (lane & 7)];
    s += __shfl_xor_sync(0xffffffffu, s, 8);
    s += __shfl_xor_sync(0xffffffffu, s, 16);
    int dg = end - beg;
    if (lane < 8) g_loop8[d * 8 + lane] = s / (float)max(dg, 1);
    if (lane == 0) g_ebs[d] = (dg > 0) ? 1.0f : 0.0f;
}

// ---------------- L5: conv2-transform dual GEMM ----------------------------------------
__global__ void __launch_bounds__(256) k_gemm2b(const float* __restrict__ Wl2,
                                                const float* __restrict__ bl2,
                                                const float* __restrict__ Wr2,
                                                const float* __restrict__ br2) {
    dev_gemm2(g_h1, Wl2, bl2, Wr2, br2, g_xl2, g_xr2, 256, 64, blockIdx.x * 128, 0);
}

// ---------------- conv1: warp-per-dst, EDGE-TRIPLE unroll (~1/3 LDS crossbar) -----------
__device__ __forceinline__ void conv1_logits_single(const float (&xls)[8], const float (&attr)[8],
                                                    float ebsc, const float (&xr)[8], int lane,
                                                    const float* __restrict__ sEW,
                                                    const float* __restrict__ seb,
                                                    const float* __restrict__ satt,
                                                    float (&out)[4]) {
    float p[4] = {0.f, 0.f, 0.f, 0.f};
#pragma unroll
    for (int t = 0; t < 8; t++) {
        int c = lane + 32 * t;
        float ep = ebsc * seb[c];
#pragma unroll
        for (int j = 0; j < 8; j++) ep += attr[j] * sEW[j * 256 + c];
        float v = xls[t] + xr[t] + ep;
        float m = v > 0.f ? v : 0.2f * v;
        p[t >> 1] += m * satt[(t >> 1) * 64 + (c & 63)];
    }
#pragma unroll
    for (int h = 0; h < 4; h++) {
#pragma unroll
        for (int off = 16; off > 0; off >>= 1)
            p[h] += __shfl_xor_sync(0xffffffffu, p[h], off);
        out[h] = p[h];
    }
}

__global__ void __launch_bounds__(256) k_conv1(const float* __restrict__ att1,
                                               const float* __restrict__ bias1) {
    __shared__ float sEW[2048];
    __shared__ float seb[256];
    __shared__ float satt[256];
    __shared__ float sbias[256];
    int tid = threadIdx.x;
    for (int i = tid; i < 2048; i += 256) sEW[i] = g_EW1[i];
    seb[tid] = g_eb1[tid];
    satt[tid] = att1[tid];
    sbias[tid] = bias1[tid];
    __syncthreads();

    int lane = tid & 31;
    int d = blockIdx.x * 8 + (tid >> 5);
    if (d >= NN) return;

    int beg = g_rowptr[d], end = g_rowptr[d + 1];

    float xr[8];
#pragma unroll
    for (int t = 0; t < 8; t++) xr[t] = g_xr1[(size_t)d * 256 + lane + 32 * t];

    float mx[4], dn[4], acc[8];
    // self loop initializes the online state
    {
        float xls[8];
        float4 a0 = *reinterpret_cast<const float4*>(&g_loop8[d * 8]);
        float4 a1 = *reinterpret_cast<const float4*>(&g_loop8[d * 8 + 4]);
        float attr[8] = {a0.x, a0.y, a0.z, a0.w, a1.x, a1.y, a1.z, a1.w};
#pragma unroll
        for (int t = 0; t < 8; t++) xls[t] = __ldg(&g_xl1[(size_t)d * 256 + lane + 32 * t]);
        float l[4];
        conv1_logits_single(xls, attr, g_ebs[d], xr, lane, sEW, seb, satt, l);
#pragma unroll
        for (int h = 0; h < 4; h++) { mx[h] = l[h]; dn[h] = 1.0f; }
#pragma unroll
        for (int t = 0; t < 8; t++) acc[t] = xls[t];
    }
    int i = beg;
    // edge TRIPLES: one sEW read serves three edges (~1/3 crossbar), regs stay < 128
    for (; i + 2 < end; i += 3) {
        int s1 = g_esrc[i], s2 = g_esrc[i + 1], s3 = g_esrc[i + 2];
        float4 a10 = *reinterpret_cast<const float4*>(&g_eatt[(size_t)i * 8]);
        float4 a11 = *reinterpret_cast<const float4*>(&g_eatt[(size_t)i * 8 + 4]);
        float4 a20 = *reinterpret_cast<const float4*>(&g_eatt[(size_t)(i + 1) * 8]);
        float4 a21 = *reinterpret_cast<const float4*>(&g_eatt[(size_t)(i + 1) * 8 + 4]);
        float4 a30 = *reinterpret_cast<const float4*>(&g_eatt[(size_t)(i + 2) * 8]);
        float4 a31 = *reinterpret_cast<const float4*>(&g_eatt[(size_t)(i + 2) * 8 + 4]);
        float at1[8] = {a10.x, a10.y, a10.z, a10.w, a11.x, a11.y, a11.z, a11.w};
        float at2[8] = {a20.x, a20.y, a20.z, a20.w, a21.x, a21.y, a21.z, a21.w};
        float at3[8] = {a30.x, a30.y, a30.z, a30.w, a31.x, a31.y, a31.z, a31.w};
        float x1[8], x2[8], x3[8];
#pragma unroll
        for (int t = 0; t < 8; t++) {
            x1[t] = __ldg(&g_xl1[(size_t)s1 * 256 + lane + 32 * t]);
            x2[t] = __ldg(&g_xl1[(size_t)s2 * 256 + lane + 32 * t]);
            x3[t] = __ldg(&g_xl1[(size_t)s3 * 256 + lane + 32 * t]);
        }
        float p1[4] = {0.f, 0.f, 0.f, 0.f};
        float p2[4] = {0.f, 0.f, 0.f, 0.f};
        float p3[4] = {0.f, 0.f, 0.f, 0.f};
#pragma unroll
        for (int t = 0; t < 8; t++) {
            int c = lane + 32 * t;
            float eb = seb[c];
            float e1 = eb, e2 = eb, e3 = eb;
#pragma unroll
            for (int j = 0; j < 8; j++) {
                float w = sEW[j * 256 + c];
                e1 = fmaf(at1[j], w, e1);
                e2 = fmaf(at2[j], w, e2);
                e3 = fmaf(at3[j], w, e3);
            }
            float xrt = xr[t];
            float v1 = e1 + xrt + x1[t];
            float v2 = e2 + xrt + x2[t];
            float v3 = e3 + xrt + x3[t];
            v1 = fmaxf(v1, 0.2f * v1);
            v2 = fmaxf(v2, 0.2f * v2);
            v3 = fmaxf(v3, 0.2f * v3);
            float aw = satt[(t >> 1) * 64 + (c & 63)];
            p1[t >> 1] = fmaf(v1, aw, p1[t >> 1]);
            p2[t >> 1] = fmaf(v2, aw, p2[t >> 1]);
            p3[t >> 1] = fmaf(v3, aw, p3[t >> 1]);
        }
#pragma unroll
        for (int h = 0; h < 4; h++) {
#pragma unroll
            for (int off = 16; off > 0; off >>= 1) {
                p1[h] += __shfl_xor_sync(0xffffffffu, p1[h], off);
                p2[h] += __shfl_xor_sync(0xffffffffu, p2[h], off);
                p3[h] += __shfl_xor_sync(0xffffffffu, p3[h], off);
            }
        }
        float a1h[4], a2h[4], a3h[4], mul[4];
#pragma unroll
        for (int h = 0; h < 4; h++) {
            float mnew = fmaxf(fmaxf(mx[h], p1[h]), fmaxf(p2[h], p3[h]));
            mul[h] = __expf(mx[h] - mnew);
            a1h[h] = __expf(p1[h] - mnew);
            a2h[h] = __expf(p2[h] - mnew);
            a3h[h] = __expf(p3[h] - mnew);
            dn[h] = fmaf(dn[h], mul[h], a1h[h] + a2h[h] + a3h[h]);
            mx[h] = mnew;
        }
#pragma unroll
        for (int t = 0; t < 8; t++) {
            int hh = t >> 1;
            float add = fmaf(a1h[hh], x1[t], a2h[hh] * x2[t]);
            add = fmaf(a3h[hh], x3[t], add);
            acc[t] = fmaf(acc[t], mul[hh], add);
        }
    }
    // pair tail
    for (; i + 1 < end; i += 2) {
        int s1 = g_esrc[i], s2 = g_esrc[i + 1];
        float4 a10 = *reinterpret_cast<const float4*>(&g_eatt[(size_t)i * 8]);
        float4 a11 = *reinterpret_cast<const float4*>(&g_eatt[(size_t)i * 8 + 4]);
        float4 a20 = *reinterpret_cast<const float4*>(&g_eatt[(size_t)(i + 1) * 8]);
        float4 a21 = *reinterpret_cast<const float4*>(&g_eatt[(size_t)(i + 1) * 8 + 4]);
        float at1[8] = {a10.x, a10.y, a10.z, a10.w, a11.x, a11.y, a11.z, a11.w};
        float at2[8] = {a20.x, a20.y, a20.z, a20.w, a21.x, a21.y, a21.z, a21.w};
        float x1[8], x2[8];
#pragma unroll
        for (int t = 0; t < 8; t++) {
            x1[t] = __ldg(&g_xl1[(size_t)s1 * 256 + lane + 32 * t]);
            x2[t] = __ldg(&g_xl1[(size_t)s2 * 256 + lane + 32 * t]);
        }
        float p1[4] = {0.f, 0.f, 0.f, 0.f};
        float p2[4] = {0.f, 0.f, 0.f, 0.f};
#pragma unroll
        for (int t = 0; t < 8; t++) {
            int c = lane + 32 * t;
            float e1 = seb[c], e2 = e1;
#pragma unroll
            for (int j = 0; j < 8; j++) {
                float w = sEW[j * 256 + c];
                e1 = fmaf(at1[j], w, e1);
                e2 = fmaf(at2[j], w, e2);
            }
            float v1 = e1 + xr[t] + x1[t];
            float v2 = e2 + xr[t] + x2[t];
            v1 = fmaxf(v1, 0.2f * v1);
            v2 = fmaxf(v2, 0.2f * v2);
            float aw = satt[(t >> 1) * 64 + (c & 63)];
            p1[t >> 1] = fmaf(v1, aw, p1[t >> 1]);
            p2[t >> 1] = fmaf(v2, aw, p2[t >> 1]);
        }
#pragma unroll
        for (int h = 0; h < 4; h++) {
#pragma unroll
            for (int off = 16; off > 0; off >>= 1) {
                p1[h] += __shfl_xor_sync(0xffffffffu, p1[h], off);
                p2[h] += __shfl_xor_sync(0xffffffffu, p2[h], off);
            }
        }
        float a1h[4], a2h[4], mul[4];
#pragma unroll
        for (int h = 0; h < 4; h++) {
            float mnew = fmaxf(mx[h], fmaxf(p1[h], p2[h]));
            mul[h] = __expf(mx[h] - mnew);
            a1h[h] = __expf(p1[h] - mnew);
            a2h[h] = __expf(p2[h] - mnew);
            dn[h] = fmaf(dn[h], mul[h], a1h[h] + a2h[h]);
            mx[h] = mnew;
        }
#pragma unroll
        for (int t = 0; t < 8; t++)
            acc[t] = fmaf(acc[t], mul[t >> 1], fmaf(a1h[t >> 1], x1[t], a2h[t >> 1] * x2[t]));
    }
    // single tail
    if (i < end) {
        int s = g_esrc[i];
        float4 a0 = *reinterpret_cast<const float4*>(&g_eatt[(size_t)i * 8]);
        float4 a1 = *reinterpret_cast<const float4*>(&g_eatt[(size_t)i * 8 + 4]);
        float attr[8] = {a0.x, a0.y, a0.z, a0.w, a1.x, a1.y, a1.z, a1.w};
        float xls[8];
#pragma unroll
        for (int t = 0; t < 8; t++) xls[t] = __ldg(&g_xl1[(size_t)s * 256 + lane + 32 * t]);
        float l[4];
        conv1_logits_single(xls, attr, 1.0f, xr, lane, sEW, seb, satt, l);
        float a[4], mul[4];
#pragma unroll
        for (int h = 0; h < 4; h++) {
            float mnew = fmaxf(mx[h], l[h]);
            mul[h] = __expf(mx[h] - mnew);
            a[h]   = __expf(l[h] - mnew);
            dn[h]  = fmaf(dn[h], mul[h], a[h]);
            mx[h]  = mnew;
        }
#pragma unroll
        for (int t = 0; t < 8; t++) acc[t] = fmaf(acc[t], mul[t >> 1], a[t >> 1] * xls[t]);
    }
#pragma unroll
    for (int t = 0; t < 8; t++) {
        int c = lane + 32 * t;
        float o = acc[t] / (dn[t >> 1] + 1e-16f) + sbias[c];
        o = (o > 0.f) ? o : expm1f(o);   // ELU
        g_h1[(size_t)d * 256 + c] = o;
    }
}

// ---------------- conv2: EDGE-QUAD unroll (R15 proven), fused mean-pool -----------------
__device__ __forceinline__ float conv2_logit_reg(float xs0, float xs1, const float (&attr)[8],
                                                 float ebsc, float xr0, float xr1, int lane,
                                                 const float* __restrict__ sEW,
                                                 const float* __restrict__ seb,
                                                 const float* __restrict__ satt) {
    float p = 0.f;
#pragma unroll
    for (int t = 0; t < 2; t++) {
        int c = lane + 32 * t;
        float ep = ebsc * seb[c];
#pragma unroll
        for (int j = 0; j < 8; j++) ep += attr[j] * sEW[j * 64 + c];
        float v = (t == 0 ? xs0 : xs1) + (t == 0 ? xr0 : xr1) + ep;
        float m = v > 0.f ? v : 0.2f * v;
        p += m * satt[c];
    }
#pragma unroll
    for (int off = 16; off > 0; off >>= 1) p += __shfl_xor_sync(0xffffffffu, p, off);
    return p;
}

__global__ void __launch_bounds__(256) k_conv2(const float* __restrict__ att2,
                                               const float* __restrict__ bias2,
                                               const void* __restrict__ batch) {
    __shared__ float sEW[512];
    __shared__ float seb[64];
    __shared__ float satt[64];
    __shared__ float sbias[64];
    int tid = threadIdx.x;
    for (int i = tid; i < 512; i += 256) sEW[i] = g_EW2[i];
    if (tid < 64) { seb[tid] = g_eb2[tid]; satt[tid] = att2[tid]; sbias[tid] = bias2[tid]; }
    __syncthreads();

    int lane = tid & 31;
    int d = blockIdx.x * 8 + (tid >> 5);
    if (d >= NN) return;

    int beg = g_rowptr[d], end = g_rowptr[d + 1];
    float xr0 = g_xr2[(size_t)d * 64 + lane];
    float xr1 = g_xr2[(size_t)d * 64 + lane + 32];

    float mx, dn, acc0, acc1;
    {
        float4 a0 = *reinterpret_cast<const float4*>(&g_loop8[d * 8]);
        float4 a1 = *reinterpret_cast<const float4*>(&g_loop8[d * 8 + 4]);
        float attr[8] = {a0.x, a0.y, a0.z, a0.w, a1.x, a1.y, a1.z, a1.w};
        float xs0 = __ldg(&g_xl2[(size_t)d * 64 + lane]);
        float xs1 = __ldg(&g_xl2[(size_t)d * 64 + lane + 32]);
        mx = conv2_logit_reg(xs0, xs1, attr, g_ebs[d], xr0, xr1, lane, sEW, seb, satt);
        dn = 1.0f; acc0 = xs0; acc1 = xs1;
    }
    int i = beg;
    // edge QUADS: one sEW read serves four edges
    for (; i + 3 < end; i += 4) {
        int s1 = g_esrc[i], s2 = g_esrc[i + 1], s3 = g_esrc[i + 2], s4 = g_esrc[i + 3];
        float4 a10 = *reinterpret_cast<const float4*>(&g_eatt[(size_t)i * 8]);
        float4 a11 = *reinterpret_cast<const float4*>(&g_eatt[(size_t)i * 8 + 4]);
        float4 a20 = *reinterpret_cast<const float4*>(&g_eatt[(size_t)(i + 1) * 8]);
        float4 a21 = *reinterpret_cast<const float4*>(&g_eatt[(size_t)(i + 1) * 8 + 4]);
        float4 a30 = *reinterpret_cast<const float4*>(&g_eatt[(size_t)(i + 2) * 8]);
        float4 a31 = *reinterpret_cast<const float4*>(&g_eatt[(size_t)(i + 2) * 8 + 4]);
        float4 a40 = *reinterpret_cast<const float4*>(&g_eatt[(size_t)(i + 3) * 8]);
        float4 a41 = *reinterpret_cast<const float4*>(&g_eatt[(size_t)(i + 3) * 8 + 4]);
        float at1[8] = {a10.x, a10.y, a10.z, a10.w, a11.x, a11.y, a11.z, a11.w};
        float at2[8] = {a20.x, a20.y, a20.z, a20.w, a21.x, a21.y, a21.z, a21.w};
        float at3[8] = {a30.x, a30.y, a30.z, a30.w, a31.x, a31.y, a31.z, a31.w};
        float at4[8] = {a40.x, a40.y, a40.z, a40.w, a41.x, a41.y, a41.z, a41.w};
        float x10 = __ldg(&g_xl2[(size_t)s1 * 64 + lane]);
        float x11 = __ldg(&g_xl2[(size_t)s1 * 64 + lane + 32]);
        float x20 = __ldg(&g_xl2[(size_t)s2 * 64 + lane]);
        float x21 = __ldg(&g_xl2[(size_t)s2 * 64 + lane + 32]);
        float x30 = __ldg(&g_xl2[(size_t)s3 * 64 + lane]);
        float x31 = __ldg(&g_xl2[(size_t)s3 * 64 + lane + 32]);
        float x40 = __ldg(&g_xl2[(size_t)s4 * 64 + lane]);
        float x41 = __ldg(&g_xl2[(size_t)s4 * 64 + lane + 32]);
        float p1 = 0.f, p2 = 0.f, p3 = 0.f, p4 = 0.f;
#pragma unroll
        for (int t = 0; t < 2; t++) {
            int c = lane + 32 * t;
            float eb = seb[c];
            float e1 = eb, e2 = eb, e3 = eb, e4 = eb;
#pragma unroll
            for (int j = 0; j < 8; j++) {
                float w = sEW[j * 64 + c];
                e1 = fmaf(at1[j], w, e1);
                e2 = fmaf(at2[j], w, e2);
                e3 = fmaf(at3[j], w, e3);
                e4 = fmaf(at4[j], w, e4);
            }
            float xrv = (t == 0) ? xr0 : xr1;
            float v1 = e1 + xrv + ((t == 0) ? x10 : x11);
            float v2 = e2 + xrv + ((t == 0) ? x20 : x21);
            float v3 = e3 + xrv + ((t == 0) ? x30 : x31);
            float v4 = e4 + xrv + ((t == 0) ? x40 : x41);
            v1 = fmaxf(v1, 0.2f * v1);
            v2 = fmaxf(v2, 0.2f * v2);
            v3 = fmaxf(v3, 0.2f * v3);
            v4 = fmaxf(v4, 0.2f * v4);
            float aw = satt[c];
            p1 = fmaf(v1, aw, p1);
            p2 = fmaf(v2, aw, p2);
            p3 = fmaf(v3, aw, p3);
            p4 = fmaf(v4, aw, p4);
        }
#pragma unroll
        for (int off = 16; off > 0; off >>= 1) {
            p1 += __shfl_xor_sync(0xffffffffu, p1, off);
            p2 += __shfl_xor_sync(0xffffffffu, p2, off);
            p3 += __shfl_xor_sync(0xffffffffu, p3, off);
            p4 += __shfl_xor_sync(0xffffffffu, p4, off);
        }
        float mnew = fmaxf(fmaxf(mx, fmaxf(p1, p2)), fmaxf(p3, p4));
        float c  = __expf(mx - mnew);
        float a1 = __expf(p1 - mnew);
        float a2 = __expf(p2 - mnew);
        float a3 = __expf(p3 - mnew);
        float a4 = __expf(p4 - mnew);
        dn   = fmaf(dn, c, (a1 + a2) + (a3 + a4));
        float add0 = fmaf(a1, x10, a2 * x20); add0 = fmaf(a3, x30, add0); add0 = fmaf(a4, x40, add0);
        float add1 = fmaf(a1, x11, a2 * x21); add1 = fmaf(a3, x31, add1); add1 = fmaf(a4, x41, add1);
        acc0 = fmaf(acc0, c, add0);
        acc1 = fmaf(acc1, c, add1);
        mx = mnew;
    }
    // pair tail
    for (; i + 1 < end; i += 2) {
        int s1 = g_esrc[i], s2 = g_esrc[i + 1];
        float4 a10 = *reinterpret_cast<const float4*>(&g_eatt[(size_t)i * 8]);
        float4 a11 = *reinterpret_cast<const float4*>(&g_eatt[(size_t)i * 8 + 4]);
        float4 a20 = *reinterpret_cast<const float4*>(&g_eatt[(size_t)(i + 1) * 8]);
        float4 a21 = *reinterpret_cast<const float4*>(&g_eatt[(size_t)(i + 1) * 8 + 4]);
        float at1[8] = {a10.x, a10.y, a10.z, a10.w, a11.x, a11.y, a11.z, a11.w};
        float at2[8] = {a20.x, a20.y, a20.z, a20.w, a21.x, a21.y, a21.z, a21.w};
        float x10 = __ldg(&g_xl2[(size_t)s1 * 64 + lane]);
        float x11 = __ldg(&g_xl2[(size_t)s1 * 64 + lane + 32]);
        float x20 = __ldg(&g_xl2[(size_t)s2 * 64 + lane]);
        float x21 = __ldg(&g_xl2[(size_t)s2 * 64 + lane + 32]);
        float p1 = 0.f, p2 = 0.f;
#pragma unroll
        for (int t = 0; t < 2; t++) {
            int c = lane + 32 * t;
            float e1 = seb[c], e2 = e1;
#pragma unroll
            for (int j = 0; j < 8; j++) {
                float w = sEW[j * 64 + c];
                e1 = fmaf(at1[j], w, e1);
                e2 = fmaf(at2[j], w, e2);
            }
            float xrv = (t == 0) ? xr0 : xr1;
            float v1 = e1 + xrv + ((t == 0) ? x10 : x11);
            float v2 = e2 + xrv + ((t == 0) ? x20 : x21);
            v1 = fmaxf(v1, 0.2f * v1);
            v2 = fmaxf(v2, 0.2f * v2);
            float aw = satt[c];
            p1 = fmaf(v1, aw, p1);
            p2 = fmaf(v2, aw, p2);
        }
#pragma unroll
        for (int off = 16; off > 0; off >>= 1) {
            p1 += __shfl_xor_sync(0xffffffffu, p1, off);
            p2 += __shfl_xor_sync(0xffffffffu, p2, off);
        }
        float mnew = fmaxf(mx, fmaxf(p1, p2));
        float c = __expf(mx - mnew);
        float a1 = __expf(p1 - mnew);
        float a2 = __expf(p2 - mnew);
        dn   = fmaf(dn, c, a1 + a2);
        acc0 = fmaf(acc0, c, fmaf(a1, x10, a2 * x20));
        acc1 = fmaf(acc1, c, fmaf(a1, x11, a2 * x21));
        mx = mnew;
    }
    // single tail
    if (i < end) {
        int s = g_esrc[i];
        float4 a0 = *reinterpret_cast<const float4*>(&g_eatt[(size_t)i * 8]);
        float4 a1v = *reinterpret_cast<const float4*>(&g_eatt[(size_t)i * 8 + 4]);
        float attr[8] = {a0.x, a0.y, a0.z, a0.w, a1v.x, a1v.y, a1v.z, a1v.w};
        float xs0 = __ldg(&g_xl2[(size_t)s * 64 + lane]);
        float xs1 = __ldg(&g_xl2[(size_t)s * 64 + lane + 32]);
        float l = conv2_logit_reg(xs0, xs1, attr, 1.0f, xr0, xr1, lane, sEW, seb, satt);
        float mnew = fmaxf(mx, l);
        float c = __expf(mx - mnew);
        float a = __expf(l - mnew);
        dn   = fmaf(dn, c, a);
        acc0 = fmaf(acc0, c, a * xs0);
        acc1 = fmaf(acc1, c, a * xs1);
        mx = mnew;
    }
    float inv = 1.0f / (dn + 1e-16f);
    float o0 = acc0 * inv + sbias[lane];
    float o1 = acc1 * inv + sbias[lane + 32];
    int b = load_idx(batch, d, g_is64);
    b = min(max(b, 0), NB - 1);
    atomicAdd(&g_pool[b * 64 + lane], o0);
    atomicAdd(&g_pool[b * 64 + lane + 32], o1);
}

// ---------------- decoder ------------------------------------------------------------
__global__ void k_decoder(const float* __restrict__ Wd1, const float* __restrict__ bd1,
                          const float* __restrict__ Wd2, const float* __restrict__ bd2,
                          float* __restrict__ out) {
    int b = threadIdx.x;
    if (b >= NB) return;
    float inv = 1.0f / fmaxf(g_cnt[b], 1.0f);
    float p[64];
#pragma unroll
    for (int i = 0; i < 64; i++) p[i] = g_pool[b * 64 + i] * inv;
    float o0 = bd2[0], o1 = bd2[1];
    for (int j = 0; j < 64; j++) {
        float s = bd1[j];
#pragma unroll
        for (int i = 0; i < 64; i++) s += p[i] * Wd1[i * 64 + j];
        s = fmaxf(s, 0.f);
        o0 += s * Wd2[j * 2 + 0];
        o1 += s * Wd2[j * 2 + 1];
    }
    out[b * 2 + 0] = 1.0f / (1.0f + expf(-o0));
    out[b * 2 + 1] = 1.0f / (1.0f + expf(-o1));
}

// ---------------- launch ---------------------------------------------------------------
extern "C" void kernel_launch(void* const* d_in, const int* in_sizes, int n_in,
                              void* d_out, int out_size) {
    const float* x      = (const float*)d_in[0];
    const void*  ei     = d_in[1];
    const float* eattr  = (const float*)d_in[2];
    const void*  batch  = d_in[3];
    const float* W_node = (const float*)d_in[4];
    const float* b_node = (const float*)d_in[5];
    const float* W_edge = (const float*)d_in[6];
    const float* b_edge = (const float*)d_in[7];
    const float* Wl1 = (const float*)d_in[8];
    const float* bl1 = (const float*)d_in[9];
    const float* Wr1 = (const float*)d_in[10];
    const float* br1 = (const float*)d_in[11];
    const float* We1 = (const float*)d_in[12];
    const float* att1 = (const float*)d_in[13];
    const float* bias1 = (const float*)d_in[14];
    const float* Wl2 = (const float*)d_in[15];
    const float* bl2 = (const float*)d_in[16];
    const float* Wr2 = (const float*)d_in[17];
    const float* br2 = (const float*)d_in[18];
    const float* We2 = (const float*)d_in[19];
    const float* att2 = (const float*)d_in[20];
    const float* bias2 = (const float*)d_in[21];
    const float* Wd1 = (const float*)d_in[22];
    const float* bd1 = (const float*)d_in[23];
    const float* Wd2 = (const float*)d_in[24];
    const float* bd2 = (const float*)d_in[25];

    k_init<<<256, 256>>>((const int*)ei);
    k_phase1<<<PH1_B, 256>>>(ei, batch, x, W_node, b_node, W_edge, b_edge, We1, We2);
    k_scan<<<1, 1024>>>();
    k_phase3<<<PH3_B, 256>>>(eattr, Wl1, bl1, Wr1, br1);
    k_loopattr<<<(NN + 7) / 8, 256>>>();
    k_conv1<<<(NN + 7) / 8, 256>>>(att1, bias1);
    k_gemm2b<<<G2X, 256>>>(Wl2, bl2, Wr2, br2);
    k_conv2<<<(NN + 7) / 8, 256>>>(att2, bias2, batch);
    k_decoder<<<1, 64>>>(Wd1, bd1, Wd2, bd2, (float*)d_out);
}